// round 13
// baseline (speedup 1.0000x reference)
#include <cuda_runtime.h>
#include <cuda_fp16.h>
#include <cstdint>

#define NEGV (-1e30f)

// ============================ scratch (device globals) ============================
static __device__ __align__(16) __half g_xhi[33554432], g_xlo[33554432];
static __device__ __align__(16) __half g_yhi[33554432], g_ylo[33554432];
static __device__ __align__(16) __half g_xThi[33554432], g_yThi[33554432];  // hi-only transposed
static __device__ __align__(16) __half g_wxhi[1048576], g_wxlo[1048576];
static __device__ __align__(16) __half g_wyhi[1048576], g_wylo[1048576];
static __device__ __align__(16) __half g_pxhi[33554432], g_pxlo[33554432];
static __device__ __align__(16) __half g_pyhi[33554432];
static __device__ __align__(16) float  g_s[67108864];
static __device__ __align__(16) __half g_Phi[67108864], g_Plo[67108864];
static __device__ __align__(16) __half g_Pchi[67108864], g_Pclo[67108864];
static __device__ __align__(16) float g_meanX[16384], g_meanY[16384];
static __device__ __align__(16) int   g_idxX[32768], g_idxY[32768];
static __device__ __align__(16) int   g_cntX[16], g_cntXp[16], g_cntY[16], g_cntYp[16];
static __device__ int   g_mask_mode;

// ============================ helpers =============================================
static __device__ __forceinline__ uint32_t smem_u32(const void* p) {
    uint32_t a;
    asm("{ .reg .u64 t; cvta.to.shared.u64 t, %1; cvt.u32.u64 %0, t; }" : "=r"(a) : "l"(p));
    return a;
}
__device__ __forceinline__ int c_cnt(int v)  { return v < 0 ? 0 : (v > 2048 ? 2048 : v); }
__device__ __forceinline__ int c_pad(int v)  {
    v &= ~127;
    return v < 128 ? 128 : (v > 2048 ? 2048 : v);
}
__device__ __forceinline__ int c_idx(int v)  { return v < 0 ? 0 : (v > 2047 ? 2047 : v); }

#define LDSM4(R, A)                                                                   \
    asm volatile("ldmatrix.sync.aligned.m8n8.x4.shared.b16 {%0,%1,%2,%3}, [%4];"      \
        : "=r"((R)[0]), "=r"((R)[1]), "=r"((R)[2]), "=r"((R)[3]) : "r"(A))

#define MMA_F16(C, A, B0, B1)                                                         \
    asm volatile("mma.sync.aligned.m16n8k16.row.col.f32.f16.f16.f32 "                 \
        "{%0,%1,%2,%3},{%4,%5,%6,%7},{%8,%9},{%0,%1,%2,%3};"                          \
        : "+f"((C)[0]), "+f"((C)[1]), "+f"((C)[2]), "+f"((C)[3])                      \
        : "r"((A)[0]), "r"((A)[1]), "r"((A)[2]), "r"((A)[3]), "r"(B0), "r"(B1))

__device__ __forceinline__ bool mask_at(const void* p, int idx, int mode) {
    if (mode == 0) return ((const unsigned char*)p)[idx] != 0;
    if (mode == 1) return ((const int*)p)[idx] != 0;
    return ((const float*)p)[idx] != 0.0f;
}

__device__ __forceinline__ void split2h(float v, __half& h, __half& l) {
    h = __float2half_rn(v);
    l = __float2half_rn(v - __half2float(h));
}

// ========= build unmasked index lists for BOTH masks (+ dtype detection) ==========
__global__ void build_idx_kernel(const void* __restrict__ xm, const void* __restrict__ ym) {
    const int whichm = blockIdx.x >> 4;
    const int b = blockIdx.x & 15;
    const void* mask = whichm ? ym : xm;
    const int t = threadIdx.x;                 // 256
    __shared__ int smode;
    __shared__ int scnt[256];
    if (t == 0) {
        const unsigned char* mb = (const unsigned char*)mask;
        unsigned a1 = 0, a3 = 0;
        for (int k = 0; k < 4096; k += 4) { a1 |= mb[k + 1]; a3 |= mb[k + 3]; }
        smode = a1 ? 0 : (a3 ? 2 : 1);
        if (b == 0 && whichm == 0) g_mask_mode = smode;
    }
    __syncthreads();
    const int mode = smode;
    const int base = b * 2048 + t * 8;
    int fl[8], c = 0;
#pragma unroll
    for (int r = 0; r < 8; r++) { fl[r] = mask_at(mask, base + r, mode) ? 0 : 1; c += fl[r]; }
    scnt[t] = c;
    __syncthreads();
    for (int ofs = 1; ofs < 256; ofs <<= 1) {
        int v = (t >= ofs) ? scnt[t - ofs] : 0;
        __syncthreads();
        scnt[t] += v;
        __syncthreads();
    }
    int pos = scnt[t] - c;
    int* idx = (whichm ? g_idxY : g_idxX) + b * 2048;
#pragma unroll
    for (int r = 0; r < 8; r++) if (fl[r]) idx[pos++] = t * 8 + r;
    __syncthreads();
    const int total = c_cnt(scnt[255]);
    for (int i = total + t; i < 2048; i += 256) idx[i] = 0;
    if (t == 255) {
        (whichm ? g_cntY : g_cntX)[b] = total;
        (whichm ? g_cntYp : g_cntXp)[b] = c_pad(total + 127);
    }
}

// ====================== weight split kernel (both weights) ========================
__global__ void split_plain_kernel(const float* __restrict__ Wx, const float* __restrict__ Wy) {
    const int blk = blockIdx.x;          // 2048: first 1024 Wx, rest Wy
    const int wsel = blk >> 10;
    const float* src = wsel ? Wy : Wx;
    __half* H = wsel ? g_wyhi : g_wxhi;
    __half* L = wsel ? g_wylo : g_wxlo;
    int i4 = ((blk & 1023) * 256 + threadIdx.x) * 4;
    float4 v = *reinterpret_cast<const float4*>(src + i4);
    __half h0, l0, h1, l1, h2, l2, h3, l3;
    split2h(v.x, h0, l0); split2h(v.y, h1, l1); split2h(v.z, h2, l2); split2h(v.w, h3, l3);
    ushort4 Hp = { __half_as_ushort(h0), __half_as_ushort(h1),
                   __half_as_ushort(h2), __half_as_ushort(h3) };
    ushort4 Lp = { __half_as_ushort(l0), __half_as_ushort(l1),
                   __half_as_ushort(l2), __half_as_ushort(l3) };
    *reinterpret_cast<ushort4*>(H + i4) = Hp;
    *reinterpret_cast<ushort4*>(L + i4) = Lp;
}

// ====== gather + split + transpose for BOTH tensors (z<16 -> x, z>=16 -> y) =======
__global__ void gather_split_both_kernel(const float* __restrict__ x, const float* __restrict__ y) {
    const int zz = blockIdx.z;
    const int isx = (zz < 16) ? 1 : 0;
    const int b = zz & 15;
    const float* src = isx ? x : y;
    const int cnt  = c_cnt((isx ? g_cntX  : g_cntY )[b]);
    const int cntp = c_pad((isx ? g_cntXp : g_cntYp)[b]);
    const int r0 = blockIdx.y * 64;
    if (r0 >= cntp) return;
    const int c0 = blockIdx.x * 64;
    __half* H  = isx ? g_xhi  : g_yhi;
    __half* L  = isx ? g_xlo  : g_ylo;
    __half* HT = isx ? g_xThi : g_yThi;
    const int* ib = (isx ? g_idxX : g_idxY) + b * 2048;
    __shared__ float sm[64][65];
    const int t = threadIdx.x;
    const float* S = src + (size_t)b * 2048 * 1024;
#pragma unroll
    for (int k = 0; k < 16; k++) {
        int id = k * 256 + t;
        int r = id >> 6, c = id & 63;
        int gr = r0 + r;
        float v = 0.0f;
        if (gr < cnt) v = S[(size_t)c_idx(ib[gr]) * 1024 + c0 + c];
        sm[r][c] = v;
    }
    __syncthreads();
    __half* Hb = H + (size_t)b * 2048 * 1024;
    __half* Lb = L + (size_t)b * 2048 * 1024;
#pragma unroll
    for (int k = 0; k < 4; k++) {
        int id = k * 1024 + t * 4;
        int r = id >> 6, c = id & 63;
        __half h[4], l[4];
#pragma unroll
        for (int q = 0; q < 4; q++) split2h(sm[r][c + q], h[q], l[q]);
        ushort4 Hp = { __half_as_ushort(h[0]), __half_as_ushort(h[1]),
                       __half_as_ushort(h[2]), __half_as_ushort(h[3]) };
        ushort4 Lp = { __half_as_ushort(l[0]), __half_as_ushort(l[1]),
                       __half_as_ushort(l[2]), __half_as_ushort(l[3]) };
        size_t o = (size_t)(r0 + r) * 1024 + c0 + c;
        *reinterpret_cast<ushort4*>(Hb + o) = Hp;
        *reinterpret_cast<ushort4*>(Lb + o) = Lp;
    }
    __half* HTb = HT + (size_t)b * 1024 * 2048;
#pragma unroll
    for (int k = 0; k < 4; k++) {
        int id = k * 1024 + t * 4;
        int c = id >> 6, r = id & 63;
        __half h[4];
#pragma unroll
        for (int q = 0; q < 4; q++) h[q] = __float2half_rn(sm[r + q][c]);
        ushort4 Hp = { __half_as_ushort(h[0]), __half_as_ushort(h[1]),
                       __half_as_ushort(h[2]), __half_as_ushort(h[3]) };
        size_t o = (size_t)(c0 + c) * 2048 + r0 + r;
        *reinterpret_cast<ushort4*>(HTb + o) = Hp;
    }
}

// ============================ fused row softmax (compact) =========================
__global__ void row_softmax_kernel() {
    const int b = blockIdx.y;
    const int row = blockIdx.x;
    if (row >= c_pad(g_cntXp[b])) return;
    const int nYp = c_pad(g_cntYp[b]);
    const float* sp = g_s + (size_t)b * 2048 * 2048 + (size_t)row * 2048;
    const int t = threadIdx.x;
    const bool act = (t * 8) < nYp;
    float v[8];
    if (act) {
        *reinterpret_cast<float4*>(&v[0]) = *reinterpret_cast<const float4*>(sp + t * 8);
        *reinterpret_cast<float4*>(&v[4]) = *reinterpret_cast<const float4*>(sp + t * 8 + 4);
    } else {
#pragma unroll
        for (int r = 0; r < 8; r++) v[r] = NEGV;
    }
    float m = v[0];
#pragma unroll
    for (int r = 1; r < 8; r++) m = fmaxf(m, v[r]);
    __shared__ float red[256];
    red[t] = m; __syncthreads();
    for (int s = 128; s > 0; s >>= 1) { if (t < s) red[t] = fmaxf(red[t], red[t + s]); __syncthreads(); }
    const float rm = red[0]; __syncthreads();
    float p[8], sum = 0.f;
#pragma unroll
    for (int r = 0; r < 8; r++) { p[r] = __expf(v[r] - rm); sum += p[r]; }
    red[t] = sum; __syncthreads();
    for (int s = 128; s > 0; s >>= 1) { if (t < s) red[t] += red[t + s]; __syncthreads(); }
    const float ri = (red[0] > 0.f) ? 1.0f / red[0] : 0.f;
    if (!act) return;
    size_t o = (size_t)b * 2048 * 2048 + (size_t)row * 2048 + t * 8;
#pragma unroll
    for (int g = 0; g < 2; g++) {
        __half h[4], l[4];
#pragma unroll
        for (int q = 0; q < 4; q++) split2h(p[g * 4 + q] * ri, h[q], l[q]);
        ushort4 Hp = { __half_as_ushort(h[0]), __half_as_ushort(h[1]),
                       __half_as_ushort(h[2]), __half_as_ushort(h[3]) };
        ushort4 Lp = { __half_as_ushort(l[0]), __half_as_ushort(l[1]),
                       __half_as_ushort(l[2]), __half_as_ushort(l[3]) };
        *reinterpret_cast<ushort4*>(g_Phi + o + g * 4) = Hp;
        *reinterpret_cast<ushort4*>(g_Plo + o + g * 4) = Lp;
    }
}

// ============== fused col softmax: stats + exp + transpose in ONE kernel ==========
// grid (64 j-strips, 16 b), block (32, 8)
__global__ void colsoft_kernel() {
    const int b = blockIdx.y;
    const int j0 = blockIdx.x * 32;
    const int nYp = c_pad(g_cntYp[b]);
    if (j0 >= nYp) return;
    const int nXp = c_pad(g_cntXp[b]);
    const int tx = threadIdx.x, ty = threadIdx.y;
    const int j = j0 + tx;
    const float* S = g_s + (size_t)b * 2048 * 2048;

    // phase 1: column stats over i < nXp
    float m = -3e38f;
    for (int i = ty; i < nXp; i += 8) m = fmaxf(m, S[(size_t)i * 2048 + j]);
    __shared__ float red[8][32];
    red[ty][tx] = m; __syncthreads();
    if (ty == 0) {
        float mm = red[0][tx];
#pragma unroll
        for (int r = 1; r < 8; r++) mm = fmaxf(mm, red[r][tx]);
        red[0][tx] = mm;
    }
    __syncthreads();
    const float cm = red[0][tx]; __syncthreads();
    float sum = 0.f;
    for (int i = ty; i < nXp; i += 8) sum += __expf(S[(size_t)i * 2048 + j] - cm);
    red[ty][tx] = sum; __syncthreads();
    if (ty == 0) {
        float ss = red[0][tx];
#pragma unroll
        for (int r = 1; r < 8; r++) ss += red[r][tx];
        red[0][tx] = ss;
    }
    __syncthreads();
    const float sv = red[0][tx];
    const float ci = (sv > 0.f) ? 1.0f / sv : 0.f;
    __syncthreads();

    // phase 2: exp + transpose, 32x32 tiles
    __shared__ float sm[32][33];
    for (int i0 = 0; i0 < nXp; i0 += 32) {
#pragma unroll
        for (int k = 0; k < 4; k++) {
            int i = ty * 4 + k;
            float v = S[(size_t)(i0 + i) * 2048 + j];
            sm[tx][i] = __expf(v - cm) * ci;
        }
        __syncthreads();
#pragma unroll
        for (int k = 0; k < 4; k++) {
            int jj = ty * 4 + k;
            float v = sm[jj][tx];
            __half h, l; split2h(v, h, l);
            size_t o = (size_t)b * 2048 * 2048 + (size_t)(j0 + jj) * 2048 + i0 + tx;
            g_Pchi[o] = h; g_Pclo[o] = l;
        }
        __syncthreads();
    }
}

// ============================ mean + fill kernels (merged) ========================
__global__ void mean_kernel(const float* __restrict__ x, const float* __restrict__ y) {
    const int zz = blockIdx.y;
    const int b = zz & 15;
    const float* src = (zz < 16) ? y : x;
    float* dst = (zz < 16) ? g_meanY : g_meanX;
    const int d = blockIdx.x * 256 + threadIdx.x;
    const float* S = src + (size_t)b * 2048 * 1024 + d;
    float s0 = 0, s1 = 0, s2 = 0, s3 = 0;
    for (int i = 0; i < 2048; i += 4) {
        s0 += S[(size_t)i * 1024];
        s1 += S[(size_t)(i + 1) * 1024];
        s2 += S[(size_t)(i + 2) * 1024];
        s3 += S[(size_t)(i + 3) * 1024];
    }
    dst[b * 1024 + d] = (s0 + s1 + s2 + s3) * (1.0f / 2048.0f);
}

__global__ void mean_fill_kernel(const void* __restrict__ xm, const void* __restrict__ ym,
                                 float* __restrict__ out) {
    const int zz = blockIdx.y;
    const int b = zz & 15;
    const void* mask = (zz < 16) ? xm : ym;
    const float* mean = (zz < 16) ? g_meanY : g_meanX;
    float* dst = out + ((zz < 16) ? 0 : 33554432);
    const int i = blockIdx.x;
    if (!mask_at(mask, b * 2048 + i, g_mask_mode)) return;
    const int t = threadIdx.x;
    float4 v = *reinterpret_cast<const float4*>(mean + b * 1024 + t * 4);
    *reinterpret_cast<float4*>(dst + (size_t)b * 2048 * 1024 + (size_t)i * 1024 + t * 4) = v;
}

// ===== HMMA split GEMM: 3-stage single-sync pipeline, swizzled smem, occ 2 ========
// which: 0 = merged proj (3-term), 2 = score (2-term), 3 = merged attn (2-term)
__global__ __launch_bounds__(256, 2)
void gemm_hmma_kernel(int which, float* __restrict__ Cout)
{
    const int zz = blockIdx.z;
    const int sel = (which == 2) ? 0 : (zz >> 4);
    const int b = (which == 2) ? zz : (zz & 15);
    const int m0 = blockIdx.y * 128, n0 = blockIdx.x * 128;

    const __half *Ah, *Al, *Bh, *Bl;
    __half *Chi = nullptr, *Clo = nullptr;
    float* C = Cout;
    int lda, ldb, K, ldc, mode;
    int Mlim, Nlim = 1 << 30;
    int cRow = 0, cCol = 0;
    int nt3 = 0, wlo = 1;
    const int* scat = nullptr;
    size_t sAb, sBb, cOff;

    if (which == 0) {
        nt3 = 1;
        if (sel == 0) { Ah = g_xhi; Al = g_xlo; Bh = g_wxhi; Bl = g_wxlo;
                        Mlim = c_pad(g_cntXp[b]); Chi = g_pxhi; Clo = g_pxlo; }
        else          { Ah = g_yhi; Al = g_ylo; Bh = g_wyhi; Bl = g_wylo;
                        Mlim = c_pad(g_cntYp[b]); Chi = g_pyhi; Clo = g_pyhi; wlo = 0; }
        lda = 1024; ldb = 1024; K = 1024; ldc = 1024; mode = 0;
        sAb = (size_t)2048 * 1024; sBb = 0; cOff = (size_t)b * 2048 * 1024;
    } else if (which == 2) {
        Ah = g_pxhi; Al = g_pxlo; Bh = g_pyhi; Bl = g_pyhi;
        lda = 1024; ldb = 1024; K = 1024; ldc = 2048; mode = 1;
        Mlim = c_pad(g_cntXp[b]); Nlim = c_pad(g_cntYp[b]);
        cRow = c_cnt(g_cntX[b]); cCol = c_cnt(g_cntY[b]);
        C = g_s; sAb = (size_t)2048 * 1024; sBb = (size_t)2048 * 1024;
        cOff = (size_t)b * 2048 * 2048;
    } else {
        if (sel == 0) {
            Ah = g_Phi; Al = g_Plo; Bh = g_yThi; Bl = g_yThi;
            Mlim = c_pad(g_cntXp[b]); K = c_pad(g_cntYp[b]);
            cRow = c_cnt(g_cntX[b]); scat = g_idxX + b * 2048;
            cOff = (size_t)b * 2048 * 1024;
        } else {
            Ah = g_Pchi; Al = g_Pclo; Bh = g_xThi; Bl = g_xThi;
            Mlim = c_pad(g_cntYp[b]); K = c_pad(g_cntXp[b]);
            cRow = c_cnt(g_cntY[b]); scat = g_idxY + b * 2048;
            cOff = (size_t)33554432 + (size_t)b * 2048 * 1024;
        }
        lda = 2048; ldb = 2048; ldc = 1024; mode = 2;
        sAb = (size_t)2048 * 2048; sBb = (size_t)1024 * 2048;
    }
    if (m0 >= Mlim || n0 >= Nlim) return;

    extern __shared__ __align__(16) char smem_raw[];
    const uint32_t sb = smem_u32(smem_raw);
    const int tid = threadIdx.x, wid = tid >> 5, lane = tid & 31;
    const int warp_m = wid & 3, warp_n = wid >> 2;

    const __half* tp[4] = {
        Ah + (size_t)b * sAb + (size_t)m0 * lda,
        Al + (size_t)b * sAb + (size_t)m0 * lda,
        Bh + (size_t)b * sBb + (size_t)n0 * ldb,
        Bl + (size_t)b * sBb + (size_t)n0 * ldb
    };

    float acc[2][8][4];
#pragma unroll
    for (int i = 0; i < 2; i++)
#pragma unroll
        for (int j = 0; j < 8; j++)
#pragma unroll
            for (int q = 0; q < 4; q++) acc[i][j][q] = 0.0f;

    const int rowA = warp_m * 32 + (lane & 7) + ((lane >> 3) & 1) * 8;
    const int cA = (rowA >> 1) & 3;
    const uint32_t aoff = (uint32_t)rowA * 64 + (uint32_t)((((lane >> 4) & 1) ^ (cA & 1)) * 16);
    const uint32_t sxA = (uint32_t)(cA >> 1);
    const int rowB = warp_n * 64 + (lane & 7) + ((lane >> 4) & 1) * 8;
    const int cB = (rowB >> 1) & 3;
    const uint32_t boff = (uint32_t)rowB * 64 + (uint32_t)((((lane >> 3) & 1) ^ (cB & 1)) * 16);
    const uint32_t sxB = (uint32_t)(cB >> 1);

    const int NC = K >> 5;    // clamped K -> NC in [4,64]
    const int nld = nt3 ? 8 : 6;
    const uint32_t SS = nt3 ? 32768u : 24576u;   // stage stride

    auto load_chunk = [&](int ch, int buf) {
#pragma unroll
        for (int i = 0; i < 8; i++) {
            if (i >= nld) break;
            const int o = i >> 1;
            const int idx = ((i & 1) << 8) + tid;
            const int row = idx >> 2, gr = idx & 3;
            const __half* src = tp[o] + (size_t)row * (o < 2 ? lda : ldb) + ch * 32 + gr * 8;
            const uint32_t dst = sb + (uint32_t)buf * SS + (uint32_t)o * 8192
                               + (uint32_t)row * 64 + (uint32_t)((gr ^ ((row >> 1) & 3)) * 16);
            asm volatile("cp.async.cg.shared.global [%0], [%1], 16;" :: "r"(dst), "l"(src));
        }
        asm volatile("cp.async.commit_group;");
    };

    load_chunk(0, 0);
    load_chunk(1, 1);
    int cbuf = 0, pbuf = 2;
    for (int ch = 0; ch < NC; ch++) {
        if (ch + 1 < NC) {
            asm volatile("cp.async.wait_group 1;" ::: "memory");   // chunk ch landed (this thread)
        } else {
            asm volatile("cp.async.wait_group 0;" ::: "memory");
        }
        __syncthreads();   // publishes ch to all warps AND guarantees compute(ch-1) done
        if (ch + 2 < NC) load_chunk(ch + 2, pbuf);
        const uint32_t base = sb + (uint32_t)cbuf * SS;
        if (++cbuf == 3) cbuf = 0;
        if (++pbuf == 3) pbuf = 0;
#pragma unroll
        for (int s = 0; s < 2; s++) {
            const uint32_t sA = ((uint32_t)s ^ sxA) << 5;
            const uint32_t sB = ((uint32_t)s ^ sxB) << 5;
            uint32_t a[2][2][4];
#pragma unroll
            for (int mf = 0; mf < 2; mf++) {
                LDSM4(a[mf][0], base + aoff + mf * 1024 + sA);
                LDSM4(a[mf][1], base + 8192 + aoff + mf * 1024 + sA);
            }
            uint32_t bh[2][4], bl[2][4];
            LDSM4(bh[0], base + 16384 + boff + sB);
            if (nt3) LDSM4(bl[0], base + 24576 + boff + sB);
#pragma unroll
            for (int np = 0; np < 4; np++) {
                const int cur = np & 1;
                if (np < 3) {
                    LDSM4(bh[cur ^ 1], base + 16384 + boff + (np + 1) * 1024 + sB);
                    if (nt3) LDSM4(bl[cur ^ 1], base + 24576 + boff + (np + 1) * 1024 + sB);
                }
#pragma unroll
                for (int mf = 0; mf < 2; mf++) {
#pragma unroll
                    for (int h = 0; h < 2; h++) {
                        const int nf = np * 2 + h;
                        MMA_F16(acc[mf][nf], a[mf][0], bh[cur][2 * h], bh[cur][2 * h + 1]);
                        if (nt3) MMA_F16(acc[mf][nf], a[mf][0], bl[cur][2 * h], bl[cur][2 * h + 1]);
                        MMA_F16(acc[mf][nf], a[mf][1], bh[cur][2 * h], bh[cur][2 * h + 1]);
                    }
                }
            }
        }
    }
    asm volatile("cp.async.wait_group 0;" ::: "memory");

    // ------------------------------ epilogue ------------------------------
    const int rg = m0 + warp_m * 32 + (lane >> 2);
    const int cg = n0 + warp_n * 64 + (lane & 3) * 2;

    if (mode == 0) {
        __half* CH = Chi + cOff;
        __half* CL = Clo + cOff;
#pragma unroll
        for (int mf = 0; mf < 2; mf++) {
#pragma unroll
            for (int nf = 0; nf < 8; nf++) {
                const int R = rg + mf * 16;
                const int C0 = cg + nf * 8;
                float r0 = fmaxf(acc[mf][nf][0], 0.f), r1 = fmaxf(acc[mf][nf][1], 0.f);
                float r2 = fmaxf(acc[mf][nf][2], 0.f), r3 = fmaxf(acc[mf][nf][3], 0.f);
                __half h0, l0, h1, l1, h2, l2, h3, l3;
                split2h(r0, h0, l0); split2h(r1, h1, l1);
                split2h(r2, h2, l2); split2h(r3, h3, l3);
                uint32_t hp0 = (uint32_t)__half_as_ushort(h0) | ((uint32_t)__half_as_ushort(h1) << 16);
                uint32_t hp1 = (uint32_t)__half_as_ushort(h2) | ((uint32_t)__half_as_ushort(h3) << 16);
                *reinterpret_cast<uint32_t*>(CH + (size_t)R * ldc + C0) = hp0;
                *reinterpret_cast<uint32_t*>(CH + (size_t)(R + 8) * ldc + C0) = hp1;
                if (wlo) {
                    uint32_t lp0 = (uint32_t)__half_as_ushort(l0) | ((uint32_t)__half_as_ushort(l1) << 16);
                    uint32_t lp1 = (uint32_t)__half_as_ushort(l2) | ((uint32_t)__half_as_ushort(l3) << 16);
                    *reinterpret_cast<uint32_t*>(CL + (size_t)R * ldc + C0) = lp0;
                    *reinterpret_cast<uint32_t*>(CL + (size_t)(R + 8) * ldc + C0) = lp1;
                }
            }
        }
    } else if (mode == 1) {
        float* Co = C + cOff;
#pragma unroll
        for (int mf = 0; mf < 2; mf++) {
#pragma unroll
            for (int nf = 0; nf < 8; nf++) {
                const int R0 = rg + mf * 16, R1 = R0 + 8;
                const int C0 = cg + nf * 8;
                const bool c0v = C0 < cCol, c1v = (C0 + 1) < cCol;
                const bool r0v = R0 < cRow, r1v = R1 < cRow;
                float2 w0 = { (r0v && c0v) ? acc[mf][nf][0] : NEGV,
                              (r0v && c1v) ? acc[mf][nf][1] : NEGV };
                float2 w1 = { (r1v && c0v) ? acc[mf][nf][2] : NEGV,
                              (r1v && c1v) ? acc[mf][nf][3] : NEGV };
                *reinterpret_cast<float2*>(Co + (size_t)R0 * ldc + C0) = w0;
                *reinterpret_cast<float2*>(Co + (size_t)R1 * ldc + C0) = w1;
            }
        }
    } else {
        float* Co = Cout + cOff;
        int gr[2][2];
#pragma unroll
        for (int mf = 0; mf < 2; mf++)
#pragma unroll
            for (int h = 0; h < 2; h++) {
                const int R = rg + mf * 16 + h * 8;
                gr[mf][h] = (R < cRow) ? c_idx(scat[R]) : -1;
            }
#pragma unroll
        for (int mf = 0; mf < 2; mf++) {
#pragma unroll
            for (int nf = 0; nf < 8; nf++) {
                const int C0 = cg + nf * 8;
                if (gr[mf][0] >= 0) {
                    float2 w = { acc[mf][nf][0], acc[mf][nf][1] };
                    *reinterpret_cast<float2*>(Co + (size_t)gr[mf][0] * 1024 + C0) = w;
                }
                if (gr[mf][1] >= 0) {
                    float2 w = { acc[mf][nf][2], acc[mf][nf][3] };
                    *reinterpret_cast<float2*>(Co + (size_t)gr[mf][1] * 1024 + C0) = w;
                }
            }
        }
    }
}

// =================================================================================
extern "C" void kernel_launch(void* const* d_in, const int* in_sizes, int n_in,
                              void* d_out, int out_size)
{
    (void)in_sizes; (void)n_in; (void)out_size;
    const float* x  = (const float*)d_in[0];
    const float* y  = (const float*)d_in[1];
    const void*  xm = d_in[2];
    const void*  ym = d_in[3];
    const float* Wx = (const float*)d_in[4];
    const float* Wy = (const float*)d_in[5];
    float* out = (float*)d_out;

    static const int SMEM_3T = 98304;   // 3 stages x 32768 (3-term proj)
    static const int SMEM_2T = 73728;   // 3 stages x 24576 (2-term score/attn)
    cudaFuncSetAttribute(gemm_hmma_kernel, cudaFuncAttributeMaxDynamicSharedMemorySize, SMEM_3T);

    // 0-2
    build_idx_kernel<<<32, 256>>>(xm, ym);
    gather_split_both_kernel<<<dim3(16, 32, 32), 256>>>(x, y);
    split_plain_kernel<<<2048, 256>>>(Wx, Wy);
    // 3: merged projection GEMM (3-term) — ncu capture target
    gemm_hmma_kernel<<<dim3(8, 16, 32), 256, SMEM_3T>>>(0, nullptr);
    // score (2-term)
    gemm_hmma_kernel<<<dim3(16, 16, 16), 256, SMEM_2T>>>(2, nullptr);
    // softmax passes
    row_softmax_kernel<<<dim3(2048, 16), 256>>>();
    colsoft_kernel<<<dim3(64, 16), dim3(32, 8)>>>();
    // merged attention GEMMs (2-term, scatter epilogues)
    gemm_hmma_kernel<<<dim3(8, 16, 32), 256, SMEM_2T>>>(3, out);
    // masked rows: exact means
    mean_kernel<<<dim3(4, 32), 256>>>(x, y);
    mean_fill_kernel<<<dim3(2048, 32), 256>>>(xm, ym, out);
}

// round 14
// speedup vs baseline: 1.4735x; 1.4735x over previous
#include <cuda_runtime.h>
#include <cuda_fp16.h>
#include <cstdint>

#define NEGV (-1e30f)

// ============================ scratch (device globals) ============================
static __device__ __align__(16) __half g_xhi[33554432], g_xlo[33554432];
static __device__ __align__(16) __half g_yhi[33554432], g_ylo[33554432];
static __device__ __align__(16) __half g_xThi[33554432], g_yThi[33554432];  // hi-only transposed
static __device__ __align__(16) __half g_wxhi[1048576], g_wxlo[1048576];
static __device__ __align__(16) __half g_wyhi[1048576], g_wylo[1048576];
static __device__ __align__(16) __half g_pxhi[33554432], g_pxlo[33554432];
static __device__ __align__(16) __half g_pyhi[33554432], g_pylo[33554432];
static __device__ __align__(16) float  g_s[67108864];
static __device__ __align__(16) __half g_Phi[67108864], g_Plo[67108864];
static __device__ __align__(16) __half g_Pchi[67108864], g_Pclo[67108864];
static __device__ __align__(16) float g_meanX[16384], g_meanY[16384];
static __device__ __align__(16) int   g_idxX[32768], g_idxY[32768];
static __device__ __align__(16) int   g_cntX[16], g_cntXp[16], g_cntY[16], g_cntYp[16];
static __device__ int   g_mask_mode;

// ============================ helpers =============================================
static __device__ __forceinline__ uint32_t smem_u32(const void* p) {
    uint32_t a;
    asm("{ .reg .u64 t; cvta.to.shared.u64 t, %1; cvt.u32.u64 %0, t; }" : "=r"(a) : "l"(p));
    return a;
}
__device__ __forceinline__ int c_cnt(int v)  { return v < 0 ? 0 : (v > 2048 ? 2048 : v); }
__device__ __forceinline__ int c_pad(int v)  {
    v &= ~127;
    return v < 128 ? 128 : (v > 2048 ? 2048 : v);
}
__device__ __forceinline__ int c_idx(int v)  { return v < 0 ? 0 : (v > 2047 ? 2047 : v); }

#define LDSM4(R, A)                                                                   \
    asm volatile("ldmatrix.sync.aligned.m8n8.x4.shared.b16 {%0,%1,%2,%3}, [%4];"      \
        : "=r"((R)[0]), "=r"((R)[1]), "=r"((R)[2]), "=r"((R)[3]) : "r"(A))

#define MMA_F16(C, A, B0, B1)                                                         \
    asm volatile("mma.sync.aligned.m16n8k16.row.col.f32.f16.f16.f32 "                 \
        "{%0,%1,%2,%3},{%4,%5,%6,%7},{%8,%9},{%0,%1,%2,%3};"                          \
        : "+f"((C)[0]), "+f"((C)[1]), "+f"((C)[2]), "+f"((C)[3])                      \
        : "r"((A)[0]), "r"((A)[1]), "r"((A)[2]), "r"((A)[3]), "r"(B0), "r"(B1))

__device__ __forceinline__ bool mask_at(const void* p, int idx, int mode) {
    if (mode == 0) return ((const unsigned char*)p)[idx] != 0;
    if (mode == 1) return ((const int*)p)[idx] != 0;
    return ((const float*)p)[idx] != 0.0f;
}

__device__ __forceinline__ void split2h(float v, __half& h, __half& l) {
    h = __float2half_rn(v);
    l = __float2half_rn(v - __half2float(h));
}

// ========= build unmasked index lists for BOTH masks (+ dtype detection) ==========
__global__ void build_idx_kernel(const void* __restrict__ xm, const void* __restrict__ ym) {
    const int whichm = blockIdx.x >> 4;
    const int b = blockIdx.x & 15;
    const void* mask = whichm ? ym : xm;
    const int t = threadIdx.x;                 // 256
    __shared__ int smode;
    __shared__ int scnt[256];
    if (t == 0) {
        const unsigned char* mb = (const unsigned char*)mask;
        unsigned a1 = 0, a3 = 0;
        for (int k = 0; k < 4096; k += 4) { a1 |= mb[k + 1]; a3 |= mb[k + 3]; }
        smode = a1 ? 0 : (a3 ? 2 : 1);
        if (b == 0 && whichm == 0) g_mask_mode = smode;
    }
    __syncthreads();
    const int mode = smode;
    const int base = b * 2048 + t * 8;
    int fl[8], c = 0;
#pragma unroll
    for (int r = 0; r < 8; r++) { fl[r] = mask_at(mask, base + r, mode) ? 0 : 1; c += fl[r]; }
    scnt[t] = c;
    __syncthreads();
    for (int ofs = 1; ofs < 256; ofs <<= 1) {
        int v = (t >= ofs) ? scnt[t - ofs] : 0;
        __syncthreads();
        scnt[t] += v;
        __syncthreads();
    }
    int pos = scnt[t] - c;
    int* idx = (whichm ? g_idxY : g_idxX) + b * 2048;
#pragma unroll
    for (int r = 0; r < 8; r++) if (fl[r]) idx[pos++] = t * 8 + r;
    __syncthreads();
    const int total = c_cnt(scnt[255]);
    for (int i = total + t; i < 2048; i += 256) idx[i] = 0;
    if (t == 255) {
        (whichm ? g_cntY : g_cntX)[b] = total;
        (whichm ? g_cntYp : g_cntXp)[b] = c_pad(total + 127);
    }
}

// ====================== weight split kernel (both weights) ========================
__global__ void split_plain_kernel(const float* __restrict__ Wx, const float* __restrict__ Wy) {
    const int blk = blockIdx.x;          // 2048: first 1024 Wx, rest Wy
    const int wsel = blk >> 10;
    const float* src = wsel ? Wy : Wx;
    __half* H = wsel ? g_wyhi : g_wxhi;
    __half* L = wsel ? g_wylo : g_wxlo;
    int i4 = ((blk & 1023) * 256 + threadIdx.x) * 4;
    float4 v = *reinterpret_cast<const float4*>(src + i4);
    __half h0, l0, h1, l1, h2, l2, h3, l3;
    split2h(v.x, h0, l0); split2h(v.y, h1, l1); split2h(v.z, h2, l2); split2h(v.w, h3, l3);
    ushort4 Hp = { __half_as_ushort(h0), __half_as_ushort(h1),
                   __half_as_ushort(h2), __half_as_ushort(h3) };
    ushort4 Lp = { __half_as_ushort(l0), __half_as_ushort(l1),
                   __half_as_ushort(l2), __half_as_ushort(l3) };
    *reinterpret_cast<ushort4*>(H + i4) = Hp;
    *reinterpret_cast<ushort4*>(L + i4) = Lp;
}

// ====== gather + split + transpose for BOTH tensors (z<16 -> x, z>=16 -> y) =======
// row-major: fp16 hi/lo; transposed: fp16 hi only
__global__ void gather_split_both_kernel(const float* __restrict__ x, const float* __restrict__ y) {
    const int zz = blockIdx.z;
    const int isx = (zz < 16) ? 1 : 0;
    const int b = zz & 15;
    const float* src = isx ? x : y;
    const int cnt  = c_cnt((isx ? g_cntX  : g_cntY )[b]);
    const int cntp = c_pad((isx ? g_cntXp : g_cntYp)[b]);
    const int r0 = blockIdx.y * 64;
    if (r0 >= cntp) return;
    const int c0 = blockIdx.x * 64;
    __half* H  = isx ? g_xhi  : g_yhi;
    __half* L  = isx ? g_xlo  : g_ylo;
    __half* HT = isx ? g_xThi : g_yThi;
    const int* ib = (isx ? g_idxX : g_idxY) + b * 2048;
    __shared__ float sm[64][65];
    const int t = threadIdx.x;
    const float* S = src + (size_t)b * 2048 * 1024;
#pragma unroll
    for (int k = 0; k < 16; k++) {
        int id = k * 256 + t;
        int r = id >> 6, c = id & 63;
        int gr = r0 + r;
        float v = 0.0f;
        if (gr < cnt) v = S[(size_t)c_idx(ib[gr]) * 1024 + c0 + c];
        sm[r][c] = v;
    }
    __syncthreads();
    __half* Hb = H + (size_t)b * 2048 * 1024;
    __half* Lb = L + (size_t)b * 2048 * 1024;
#pragma unroll
    for (int k = 0; k < 4; k++) {
        int id = k * 1024 + t * 4;
        int r = id >> 6, c = id & 63;
        __half h[4], l[4];
#pragma unroll
        for (int q = 0; q < 4; q++) split2h(sm[r][c + q], h[q], l[q]);
        ushort4 Hp = { __half_as_ushort(h[0]), __half_as_ushort(h[1]),
                       __half_as_ushort(h[2]), __half_as_ushort(h[3]) };
        ushort4 Lp = { __half_as_ushort(l[0]), __half_as_ushort(l[1]),
                       __half_as_ushort(l[2]), __half_as_ushort(l[3]) };
        size_t o = (size_t)(r0 + r) * 1024 + c0 + c;
        *reinterpret_cast<ushort4*>(Hb + o) = Hp;
        *reinterpret_cast<ushort4*>(Lb + o) = Lp;
    }
    __half* HTb = HT + (size_t)b * 1024 * 2048;
#pragma unroll
    for (int k = 0; k < 4; k++) {
        int id = k * 1024 + t * 4;
        int c = id >> 6, r = id & 63;
        __half h[4];
#pragma unroll
        for (int q = 0; q < 4; q++) h[q] = __float2half_rn(sm[r + q][c]);
        ushort4 Hp = { __half_as_ushort(h[0]), __half_as_ushort(h[1]),
                       __half_as_ushort(h[2]), __half_as_ushort(h[3]) };
        size_t o = (size_t)(c0 + c) * 2048 + r0 + r;
        *reinterpret_cast<ushort4*>(HTb + o) = Hp;
    }
}

// ============================ fused row softmax (compact) =========================
__global__ void row_softmax_kernel() {
    const int b = blockIdx.y;
    const int row = blockIdx.x;
    if (row >= c_pad(g_cntXp[b])) return;
    const int nYp = c_pad(g_cntYp[b]);
    const float* sp = g_s + (size_t)b * 2048 * 2048 + (size_t)row * 2048;
    const int t = threadIdx.x;
    const bool act = (t * 8) < nYp;
    float v[8];
    if (act) {
        *reinterpret_cast<float4*>(&v[0]) = *reinterpret_cast<const float4*>(sp + t * 8);
        *reinterpret_cast<float4*>(&v[4]) = *reinterpret_cast<const float4*>(sp + t * 8 + 4);
    } else {
#pragma unroll
        for (int r = 0; r < 8; r++) v[r] = NEGV;
    }
    float m = v[0];
#pragma unroll
    for (int r = 1; r < 8; r++) m = fmaxf(m, v[r]);
    __shared__ float red[256];
    red[t] = m; __syncthreads();
    for (int s = 128; s > 0; s >>= 1) { if (t < s) red[t] = fmaxf(red[t], red[t + s]); __syncthreads(); }
    const float rm = red[0]; __syncthreads();
    float p[8], sum = 0.f;
#pragma unroll
    for (int r = 0; r < 8; r++) { p[r] = __expf(v[r] - rm); sum += p[r]; }
    red[t] = sum; __syncthreads();
    for (int s = 128; s > 0; s >>= 1) { if (t < s) red[t] += red[t + s]; __syncthreads(); }
    const float ri = (red[0] > 0.f) ? 1.0f / red[0] : 0.f;
    if (!act) return;
    size_t o = (size_t)b * 2048 * 2048 + (size_t)row * 2048 + t * 8;
#pragma unroll
    for (int g = 0; g < 2; g++) {
        __half h[4], l[4];
#pragma unroll
        for (int q = 0; q < 4; q++) split2h(p[g * 4 + q] * ri, h[q], l[q]);
        ushort4 Hp = { __half_as_ushort(h[0]), __half_as_ushort(h[1]),
                       __half_as_ushort(h[2]), __half_as_ushort(h[3]) };
        ushort4 Lp = { __half_as_ushort(l[0]), __half_as_ushort(l[1]),
                       __half_as_ushort(l[2]), __half_as_ushort(l[3]) };
        *reinterpret_cast<ushort4*>(g_Phi + o + g * 4) = Hp;
        *reinterpret_cast<ushort4*>(g_Plo + o + g * 4) = Lp;
    }
}

// ============== fused col softmax: stats + exp + transpose in ONE kernel ==========
// grid (64 j-strips, 16 b), block (32, 8)
__global__ void colsoft_kernel() {
    const int b = blockIdx.y;
    const int j0 = blockIdx.x * 32;
    const int nYp = c_pad(g_cntYp[b]);
    if (j0 >= nYp) return;
    const int nXp = c_pad(g_cntXp[b]);
    const int tx = threadIdx.x, ty = threadIdx.y;
    const int j = j0 + tx;
    const float* S = g_s + (size_t)b * 2048 * 2048;

    // phase 1: column stats over i < nXp
    float m = -3e38f;
    for (int i = ty; i < nXp; i += 8) m = fmaxf(m, S[(size_t)i * 2048 + j]);
    __shared__ float red[8][32];
    red[ty][tx] = m; __syncthreads();
    if (ty == 0) {
        float mm = red[0][tx];
#pragma unroll
        for (int r = 1; r < 8; r++) mm = fmaxf(mm, red[r][tx]);
        red[0][tx] = mm;
    }
    __syncthreads();
    const float cm = red[0][tx]; __syncthreads();
    float sum = 0.f;
    for (int i = ty; i < nXp; i += 8) sum += __expf(S[(size_t)i * 2048 + j] - cm);
    red[ty][tx] = sum; __syncthreads();
    if (ty == 0) {
        float ss = red[0][tx];
#pragma unroll
        for (int r = 1; r < 8; r++) ss += red[r][tx];
        red[0][tx] = ss;
    }
    __syncthreads();
    const float sv = red[0][tx];
    const float ci = (sv > 0.f) ? 1.0f / sv : 0.f;
    __syncthreads();

    // phase 2: exp + transpose, 32x32 tiles
    __shared__ float sm[32][33];
    for (int i0 = 0; i0 < nXp; i0 += 32) {
#pragma unroll
        for (int k = 0; k < 4; k++) {
            int i = ty * 4 + k;
            float v = S[(size_t)(i0 + i) * 2048 + j];
            sm[tx][i] = __expf(v - cm) * ci;
        }
        __syncthreads();
#pragma unroll
        for (int k = 0; k < 4; k++) {
            int jj = ty * 4 + k;
            float v = sm[jj][tx];
            __half h, l; split2h(v, h, l);
            size_t o = (size_t)b * 2048 * 2048 + (size_t)(j0 + jj) * 2048 + i0 + tx;
            g_Pchi[o] = h; g_Pclo[o] = l;
        }
        __syncthreads();
    }
}

// ============================ mean + fill kernels (merged) ========================
__global__ void mean_kernel(const float* __restrict__ x, const float* __restrict__ y) {
    const int zz = blockIdx.y;                // 0..31: <16 -> y->meanY, >=16 -> x->meanX
    const int b = zz & 15;
    const float* src = (zz < 16) ? y : x;
    float* dst = (zz < 16) ? g_meanY : g_meanX;
    const int d = blockIdx.x * 256 + threadIdx.x;
    const float* S = src + (size_t)b * 2048 * 1024 + d;
    float s0 = 0, s1 = 0, s2 = 0, s3 = 0;
    for (int i = 0; i < 2048; i += 4) {
        s0 += S[(size_t)i * 1024];
        s1 += S[(size_t)(i + 1) * 1024];
        s2 += S[(size_t)(i + 2) * 1024];
        s3 += S[(size_t)(i + 3) * 1024];
    }
    dst[b * 1024 + d] = (s0 + s1 + s2 + s3) * (1.0f / 2048.0f);
}

__global__ void mean_fill_kernel(const void* __restrict__ xm, const void* __restrict__ ym,
                                 float* __restrict__ out) {
    const int zz = blockIdx.y;                // <16: xm/meanY/out ; >=16: ym/meanX/out+33M
    const int b = zz & 15;
    const void* mask = (zz < 16) ? xm : ym;
    const float* mean = (zz < 16) ? g_meanY : g_meanX;
    float* dst = out + ((zz < 16) ? 0 : 33554432);
    const int i = blockIdx.x;
    if (!mask_at(mask, b * 2048 + i, g_mask_mode)) return;
    const int t = threadIdx.x;
    float4 v = *reinterpret_cast<const float4*>(mean + b * 1024 + t * 4);
    *reinterpret_cast<float4*>(dst + (size_t)b * 2048 * 1024 + (size_t)i * 1024 + t * 4) = v;
}

// ============ HMMA split GEMM: 3-stage pipeline, swizzled smem, occupancy 2 =======
// which: 0 = merged proj (3-term), 2 = score (3-term), 3 = merged attn (2-term)
// (R12 mainloop verbatim: constant 32KB stage stride, two-sync order)
__global__ __launch_bounds__(256, 2)
void gemm_hmma_kernel(int which, float* __restrict__ Cout)
{
    const int zz = blockIdx.z;
    const int sel = (which == 2) ? 0 : (zz >> 4);
    const int b = (which == 2) ? zz : (zz & 15);
    const int m0 = blockIdx.y * 128, n0 = blockIdx.x * 128;

    const __half *Ah, *Al, *Bh, *Bl;
    __half *Chi = nullptr, *Clo = nullptr;
    float* C = Cout;
    int lda, ldb, K, ldc, mode;
    int Mlim, Nlim = 1 << 30;
    int cRow = 0, cCol = 0;
    int nt3 = 1;
    const int* scat = nullptr;
    size_t sAb, sBb, cOff;

    if (which == 0) {
        if (sel == 0) { Ah = g_xhi; Al = g_xlo; Bh = g_wxhi; Bl = g_wxlo;
                        Mlim = c_pad(g_cntXp[b]); Chi = g_pxhi; Clo = g_pxlo; }
        else          { Ah = g_yhi; Al = g_ylo; Bh = g_wyhi; Bl = g_wylo;
                        Mlim = c_pad(g_cntYp[b]); Chi = g_pyhi; Clo = g_pylo; }
        lda = 1024; ldb = 1024; K = 1024; ldc = 1024; mode = 0;
        sAb = (size_t)2048 * 1024; sBb = 0; cOff = (size_t)b * 2048 * 1024;
    } else if (which == 2) {
        Ah = g_pxhi; Al = g_pxlo; Bh = g_pyhi; Bl = g_pylo;
        lda = 1024; ldb = 1024; K = 1024; ldc = 2048; mode = 1;
        Mlim = c_pad(g_cntXp[b]); Nlim = c_pad(g_cntYp[b]);
        cRow = c_cnt(g_cntX[b]); cCol = c_cnt(g_cntY[b]);
        C = g_s; sAb = (size_t)2048 * 1024; sBb = (size_t)2048 * 1024;
        cOff = (size_t)b * 2048 * 2048;
    } else {
        nt3 = 0;   // 2-term: (Phi + Plo) x y_hi
        if (sel == 0) {
            Ah = g_Phi; Al = g_Plo; Bh = g_yThi; Bl = g_yThi;
            Mlim = c_pad(g_cntXp[b]); K = c_pad(g_cntYp[b]);
            cRow = c_cnt(g_cntX[b]); scat = g_idxX + b * 2048;
            cOff = (size_t)b * 2048 * 1024;
        } else {
            Ah = g_Pchi; Al = g_Pclo; Bh = g_xThi; Bl = g_xThi;
            Mlim = c_pad(g_cntYp[b]); K = c_pad(g_cntXp[b]);
            cRow = c_cnt(g_cntY[b]); scat = g_idxY + b * 2048;
            cOff = (size_t)33554432 + (size_t)b * 2048 * 1024;
        }
        lda = 2048; ldb = 2048; ldc = 1024; mode = 2;
        sAb = (size_t)2048 * 2048; sBb = (size_t)1024 * 2048;
    }
    if (m0 >= Mlim || n0 >= Nlim) return;

    extern __shared__ __align__(16) char smem_raw[];
    const uint32_t sb = smem_u32(smem_raw);
    const int tid = threadIdx.x, wid = tid >> 5, lane = tid & 31;
    const int warp_m = wid & 3, warp_n = wid >> 2;

    const __half* tp[4] = {
        Ah + (size_t)b * sAb + (size_t)m0 * lda,
        Al + (size_t)b * sAb + (size_t)m0 * lda,
        Bh + (size_t)b * sBb + (size_t)n0 * ldb,
        Bl + (size_t)b * sBb + (size_t)n0 * ldb
    };

    float acc[2][8][4];
#pragma unroll
    for (int i = 0; i < 2; i++)
#pragma unroll
        for (int j = 0; j < 8; j++)
#pragma unroll
            for (int q = 0; q < 4; q++) acc[i][j][q] = 0.0f;

    const int rowA = warp_m * 32 + (lane & 7) + ((lane >> 3) & 1) * 8;
    const int cA = (rowA >> 1) & 3;
    const uint32_t aoff = (uint32_t)rowA * 64 + (uint32_t)((((lane >> 4) & 1) ^ (cA & 1)) * 16);
    const uint32_t sxA = (uint32_t)(cA >> 1);
    const int rowB = warp_n * 64 + (lane & 7) + ((lane >> 4) & 1) * 8;
    const int cB = (rowB >> 1) & 3;
    const uint32_t boff = (uint32_t)rowB * 64 + (uint32_t)((((lane >> 3) & 1) ^ (cB & 1)) * 16);
    const uint32_t sxB = (uint32_t)(cB >> 1);

    const int NC = K >> 5;    // clamped K -> NC in [4,64]
    const int nld = nt3 ? 8 : 6;

    auto load_chunk = [&](int ch, int buf) {
#pragma unroll
        for (int i = 0; i < 8; i++) {
            if (i >= nld) break;
            const int o = i >> 1;
            const int idx = ((i & 1) << 8) + tid;
            const int row = idx >> 2, gr = idx & 3;
            const __half* src = tp[o] + (size_t)row * (o < 2 ? lda : ldb) + ch * 32 + gr * 8;
            const uint32_t dst = sb + (uint32_t)buf * 32768 + (uint32_t)o * 8192
                               + (uint32_t)row * 64 + (uint32_t)((gr ^ ((row >> 1) & 3)) * 16);
            asm volatile("cp.async.cg.shared.global [%0], [%1], 16;" :: "r"(dst), "l"(src));
        }
        asm volatile("cp.async.commit_group;");
    };

    load_chunk(0, 0);
    load_chunk(1, 1);
    int cbuf = 0, pbuf = 2;
    for (int ch = 0; ch < NC; ch++) {
        __syncthreads();                         // pbuf free (consumed at ch-1)
        if (ch + 2 < NC) {
            load_chunk(ch + 2, pbuf);
            asm volatile("cp.async.wait_group 2;" ::: "memory");   // chunk ch landed
        } else if (ch + 1 < NC) {
            asm volatile("cp.async.wait_group 1;" ::: "memory");
        } else {
            asm volatile("cp.async.wait_group 0;" ::: "memory");
        }
        __syncthreads();                         // ch's data visible to all warps
        const uint32_t base = sb + (uint32_t)cbuf * 32768;
        if (++cbuf == 3) cbuf = 0;
        if (++pbuf == 3) pbuf = 0;
#pragma unroll
        for (int s = 0; s < 2; s++) {
            const uint32_t sA = ((uint32_t)s ^ sxA) << 5;
            const uint32_t sB = ((uint32_t)s ^ sxB) << 5;
            uint32_t a[2][2][4];
#pragma unroll
            for (int mf = 0; mf < 2; mf++) {
                LDSM4(a[mf][0], base + aoff + mf * 1024 + sA);
                LDSM4(a[mf][1], base + 8192 + aoff + mf * 1024 + sA);
            }
            uint32_t bh[2][4], bl[2][4];
            LDSM4(bh[0], base + 16384 + boff + sB);
            if (nt3) LDSM4(bl[0], base + 24576 + boff + sB);
#pragma unroll
            for (int np = 0; np < 4; np++) {
                const int cur = np & 1;
                if (np < 3) {
                    LDSM4(bh[cur ^ 1], base + 16384 + boff + (np + 1) * 1024 + sB);
                    if (nt3) LDSM4(bl[cur ^ 1], base + 24576 + boff + (np + 1) * 1024 + sB);
                }
#pragma unroll
                for (int mf = 0; mf < 2; mf++) {
#pragma unroll
                    for (int h = 0; h < 2; h++) {
                        const int nf = np * 2 + h;
                        MMA_F16(acc[mf][nf], a[mf][0], bh[cur][2 * h], bh[cur][2 * h + 1]);
                        if (nt3) MMA_F16(acc[mf][nf], a[mf][0], bl[cur][2 * h], bl[cur][2 * h + 1]);
                        MMA_F16(acc[mf][nf], a[mf][1], bh[cur][2 * h], bh[cur][2 * h + 1]);
                    }
                }
            }
        }
    }
    asm volatile("cp.async.wait_group 0;" ::: "memory");

    // ------------------------------ epilogue ------------------------------
    const int rg = m0 + warp_m * 32 + (lane >> 2);
    const int cg = n0 + warp_n * 64 + (lane & 3) * 2;

    if (mode == 0) {
        __half* CH = Chi + cOff;
        __half* CL = Clo + cOff;
#pragma unroll
        for (int mf = 0; mf < 2; mf++) {
#pragma unroll
            for (int nf = 0; nf < 8; nf++) {
                const int R = rg + mf * 16;
                const int C0 = cg + nf * 8;
                float r0 = fmaxf(acc[mf][nf][0], 0.f), r1 = fmaxf(acc[mf][nf][1], 0.f);
                float r2 = fmaxf(acc[mf][nf][2], 0.f), r3 = fmaxf(acc[mf][nf][3], 0.f);
                __half h0, l0, h1, l1, h2, l2, h3, l3;
                split2h(r0, h0, l0); split2h(r1, h1, l1);
                split2h(r2, h2, l2); split2h(r3, h3, l3);
                uint32_t hp0 = (uint32_t)__half_as_ushort(h0) | ((uint32_t)__half_as_ushort(h1) << 16);
                uint32_t lp0 = (uint32_t)__half_as_ushort(l0) | ((uint32_t)__half_as_ushort(l1) << 16);
                uint32_t hp1 = (uint32_t)__half_as_ushort(h2) | ((uint32_t)__half_as_ushort(h3) << 16);
                uint32_t lp1 = (uint32_t)__half_as_ushort(l2) | ((uint32_t)__half_as_ushort(l3) << 16);
                *reinterpret_cast<uint32_t*>(CH + (size_t)R * ldc + C0) = hp0;
                *reinterpret_cast<uint32_t*>(CL + (size_t)R * ldc + C0) = lp0;
                *reinterpret_cast<uint32_t*>(CH + (size_t)(R + 8) * ldc + C0) = hp1;
                *reinterpret_cast<uint32_t*>(CL + (size_t)(R + 8) * ldc + C0) = lp1;
            }
        }
    } else if (mode == 1) {
        float* Co = C + cOff;
#pragma unroll
        for (int mf = 0; mf < 2; mf++) {
#pragma unroll
            for (int nf = 0; nf < 8; nf++) {
                const int R0 = rg + mf * 16, R1 = R0 + 8;
                const int C0 = cg + nf * 8;
                const bool c0v = C0 < cCol, c1v = (C0 + 1) < cCol;
                const bool r0v = R0 < cRow, r1v = R1 < cRow;
                float2 w0 = { (r0v && c0v) ? acc[mf][nf][0] : NEGV,
                              (r0v && c1v) ? acc[mf][nf][1] : NEGV };
                float2 w1 = { (r1v && c0v) ? acc[mf][nf][2] : NEGV,
                              (r1v && c1v) ? acc[mf][nf][3] : NEGV };
                *reinterpret_cast<float2*>(Co + (size_t)R0 * ldc + C0) = w0;
                *reinterpret_cast<float2*>(Co + (size_t)R1 * ldc + C0) = w1;
            }
        }
    } else {
        float* Co = Cout + cOff;
        int gr[2][2];
#pragma unroll
        for (int mf = 0; mf < 2; mf++)
#pragma unroll
            for (int h = 0; h < 2; h++) {
                const int R = rg + mf * 16 + h * 8;
                gr[mf][h] = (R < cRow) ? c_idx(scat[R]) : -1;
            }
#pragma unroll
        for (int mf = 0; mf < 2; mf++) {
#pragma unroll
            for (int nf = 0; nf < 8; nf++) {
                const int C0 = cg + nf * 8;
                if (gr[mf][0] >= 0) {
                    float2 w = { acc[mf][nf][0], acc[mf][nf][1] };
                    *reinterpret_cast<float2*>(Co + (size_t)gr[mf][0] * 1024 + C0) = w;
                }
                if (gr[mf][1] >= 0) {
                    float2 w = { acc[mf][nf][2], acc[mf][nf][3] };
                    *reinterpret_cast<float2*>(Co + (size_t)gr[mf][1] * 1024 + C0) = w;
                }
            }
        }
    }
}

// =================================================================================
extern "C" void kernel_launch(void* const* d_in, const int* in_sizes, int n_in,
                              void* d_out, int out_size)
{
    (void)in_sizes; (void)n_in; (void)out_size;
    const float* x  = (const float*)d_in[0];
    const float* y  = (const float*)d_in[1];
    const void*  xm = d_in[2];
    const void*  ym = d_in[3];
    const float* Wx = (const float*)d_in[4];
    const float* Wy = (const float*)d_in[5];
    float* out = (float*)d_out;

    static const int SMEM_GEMM = 98304;   // 3 stages x 32768
    cudaFuncSetAttribute(gemm_hmma_kernel, cudaFuncAttributeMaxDynamicSharedMemorySize, SMEM_GEMM);

    // 0-2
    build_idx_kernel<<<32, 256>>>(xm, ym);
    gather_split_both_kernel<<<dim3(16, 32, 32), 256>>>(x, y);
    split_plain_kernel<<<2048, 256>>>(Wx, Wy);
    // 3: merged projection GEMM — ncu capture target
    gemm_hmma_kernel<<<dim3(8, 16, 32), 256, SMEM_GEMM>>>(0, nullptr);
    // score (3-term)
    gemm_hmma_kernel<<<dim3(16, 16, 16), 256, SMEM_GEMM>>>(2, nullptr);
    // softmax passes (row fused; col fused stats+exp+transpose)
    row_softmax_kernel<<<dim3(2048, 16), 256>>>();
    colsoft_kernel<<<dim3(64, 16), dim3(32, 8)>>>();
    // merged attention GEMMs (2-term, scatter epilogues)
    gemm_hmma_kernel<<<dim3(8, 16, 32), 256, SMEM_GEMM>>>(3, out);
    // masked rows: exact means
    mean_kernel<<<dim3(4, 32), 256>>>(x, y);
    mean_fill_kernel<<<dim3(2048, 32), 256>>>(xm, ym, out);
}

// round 15
// speedup vs baseline: 1.5793x; 1.0719x over previous
#include <cuda_runtime.h>
#include <cuda_fp16.h>
#include <cstdint>

#define NEGV (-1e30f)

// ============================ scratch (device globals) ============================
static __device__ __align__(16) __half g_xhi[33554432], g_xlo[33554432];
static __device__ __align__(16) __half g_yhi[33554432], g_ylo[33554432];
static __device__ __align__(16) __half g_xThi[33554432], g_yThi[33554432];  // hi-only transposed
static __device__ __align__(16) __half g_wxhi[1048576], g_wxlo[1048576];
static __device__ __align__(16) __half g_wyhi[1048576], g_wylo[1048576];
static __device__ __align__(16) __half g_pxhi[33554432], g_pxlo[33554432];
static __device__ __align__(16) __half g_pyhi[33554432], g_pylo[33554432];
static __device__ __align__(16) float  g_s[67108864];
static __device__ __align__(16) __half g_Phi[67108864], g_Plo[67108864];
static __device__ __align__(16) __half g_Pchi[67108864], g_Pclo[67108864];
static __device__ __align__(16) float g_meanX[16384], g_meanY[16384];
static __device__ __align__(16) int   g_idxX[32768], g_idxY[32768];
static __device__ __align__(16) int   g_cntX[16], g_cntXp[16], g_cntY[16], g_cntYp[16];
static __device__ int   g_mask_mode;

// ============================ helpers =============================================
static __device__ __forceinline__ uint32_t smem_u32(const void* p) {
    uint32_t a;
    asm("{ .reg .u64 t; cvta.to.shared.u64 t, %1; cvt.u32.u64 %0, t; }" : "=r"(a) : "l"(p));
    return a;
}
__device__ __forceinline__ int c_cnt(int v)  { return v < 0 ? 0 : (v > 2048 ? 2048 : v); }
__device__ __forceinline__ int c_pad(int v)  {
    v &= ~127;
    return v < 128 ? 128 : (v > 2048 ? 2048 : v);
}
__device__ __forceinline__ int c_idx(int v)  { return v < 0 ? 0 : (v > 2047 ? 2047 : v); }

#define LDSM4(R, A)                                                                   \
    asm volatile("ldmatrix.sync.aligned.m8n8.x4.shared.b16 {%0,%1,%2,%3}, [%4];"      \
        : "=r"((R)[0]), "=r"((R)[1]), "=r"((R)[2]), "=r"((R)[3]) : "r"(A))

#define MMA_F16(C, A, B0, B1)                                                         \
    asm volatile("mma.sync.aligned.m16n8k16.row.col.f32.f16.f16.f32 "                 \
        "{%0,%1,%2,%3},{%4,%5,%6,%7},{%8,%9},{%0,%1,%2,%3};"                          \
        : "+f"((C)[0]), "+f"((C)[1]), "+f"((C)[2]), "+f"((C)[3])                      \
        : "r"((A)[0]), "r"((A)[1]), "r"((A)[2]), "r"((A)[3]), "r"(B0), "r"(B1))

__device__ __forceinline__ bool mask_at(const void* p, int idx, int mode) {
    if (mode == 0) return ((const unsigned char*)p)[idx] != 0;
    if (mode == 1) return ((const int*)p)[idx] != 0;
    return ((const float*)p)[idx] != 0.0f;
}

__device__ __forceinline__ void split2h(float v, __half& h, __half& l) {
    h = __float2half_rn(v);
    l = __float2half_rn(v - __half2float(h));
}

// ========= build unmasked index lists for BOTH masks (+ dtype detection) ==========
__global__ void build_idx_kernel(const void* __restrict__ xm, const void* __restrict__ ym) {
    const int whichm = blockIdx.x >> 4;
    const int b = blockIdx.x & 15;
    const void* mask = whichm ? ym : xm;
    const int t = threadIdx.x;                 // 256
    __shared__ int smode;
    __shared__ int scnt[256];
    if (t == 0) {
        const unsigned char* mb = (const unsigned char*)mask;
        unsigned a1 = 0, a3 = 0;
        for (int k = 0; k < 4096; k += 4) { a1 |= mb[k + 1]; a3 |= mb[k + 3]; }
        smode = a1 ? 0 : (a3 ? 2 : 1);
        if (b == 0 && whichm == 0) g_mask_mode = smode;
    }
    __syncthreads();
    const int mode = smode;
    const int base = b * 2048 + t * 8;
    int fl[8], c = 0;
#pragma unroll
    for (int r = 0; r < 8; r++) { fl[r] = mask_at(mask, base + r, mode) ? 0 : 1; c += fl[r]; }
    scnt[t] = c;
    __syncthreads();
    for (int ofs = 1; ofs < 256; ofs <<= 1) {
        int v = (t >= ofs) ? scnt[t - ofs] : 0;
        __syncthreads();
        scnt[t] += v;
        __syncthreads();
    }
    int pos = scnt[t] - c;
    int* idx = (whichm ? g_idxY : g_idxX) + b * 2048;
#pragma unroll
    for (int r = 0; r < 8; r++) if (fl[r]) idx[pos++] = t * 8 + r;
    __syncthreads();
    const int total = c_cnt(scnt[255]);
    for (int i = total + t; i < 2048; i += 256) idx[i] = 0;
    if (t == 255) {
        (whichm ? g_cntY : g_cntX)[b] = total;
        (whichm ? g_cntYp : g_cntXp)[b] = c_pad(total + 127);
    }
}

// ====================== weight split kernel (both weights) ========================
__global__ void split_plain_kernel(const float* __restrict__ Wx, const float* __restrict__ Wy) {
    const int blk = blockIdx.x;          // 2048: first 1024 Wx, rest Wy
    const int wsel = blk >> 10;
    const float* src = wsel ? Wy : Wx;
    __half* H = wsel ? g_wyhi : g_wxhi;
    __half* L = wsel ? g_wylo : g_wxlo;
    int i4 = ((blk & 1023) * 256 + threadIdx.x) * 4;
    float4 v = *reinterpret_cast<const float4*>(src + i4);
    __half h0, l0, h1, l1, h2, l2, h3, l3;
    split2h(v.x, h0, l0); split2h(v.y, h1, l1); split2h(v.z, h2, l2); split2h(v.w, h3, l3);
    ushort4 Hp = { __half_as_ushort(h0), __half_as_ushort(h1),
                   __half_as_ushort(h2), __half_as_ushort(h3) };
    ushort4 Lp = { __half_as_ushort(l0), __half_as_ushort(l1),
                   __half_as_ushort(l2), __half_as_ushort(l3) };
    *reinterpret_cast<ushort4*>(H + i4) = Hp;
    *reinterpret_cast<ushort4*>(L + i4) = Lp;
}

// ====== gather + split + transpose for BOTH tensors (z<16 -> x, z>=16 -> y) =======
__global__ void gather_split_both_kernel(const float* __restrict__ x, const float* __restrict__ y) {
    const int zz = blockIdx.z;
    const int isx = (zz < 16) ? 1 : 0;
    const int b = zz & 15;
    const float* src = isx ? x : y;
    const int cnt  = c_cnt((isx ? g_cntX  : g_cntY )[b]);
    const int cntp = c_pad((isx ? g_cntXp : g_cntYp)[b]);
    const int r0 = blockIdx.y * 64;
    if (r0 >= cntp) return;
    const int c0 = blockIdx.x * 64;
    __half* H  = isx ? g_xhi  : g_yhi;
    __half* L  = isx ? g_xlo  : g_ylo;
    __half* HT = isx ? g_xThi : g_yThi;
    const int* ib = (isx ? g_idxX : g_idxY) + b * 2048;
    __shared__ float sm[64][65];
    const int t = threadIdx.x;
    const float* S = src + (size_t)b * 2048 * 1024;
#pragma unroll
    for (int k = 0; k < 16; k++) {
        int id = k * 256 + t;
        int r = id >> 6, c = id & 63;
        int gr = r0 + r;
        float v = 0.0f;
        if (gr < cnt) v = S[(size_t)c_idx(ib[gr]) * 1024 + c0 + c];
        sm[r][c] = v;
    }
    __syncthreads();
    __half* Hb = H + (size_t)b * 2048 * 1024;
    __half* Lb = L + (size_t)b * 2048 * 1024;
#pragma unroll
    for (int k = 0; k < 4; k++) {
        int id = k * 1024 + t * 4;
        int r = id >> 6, c = id & 63;
        __half h[4], l[4];
#pragma unroll
        for (int q = 0; q < 4; q++) split2h(sm[r][c + q], h[q], l[q]);
        ushort4 Hp = { __half_as_ushort(h[0]), __half_as_ushort(h[1]),
                       __half_as_ushort(h[2]), __half_as_ushort(h[3]) };
        ushort4 Lp = { __half_as_ushort(l[0]), __half_as_ushort(l[1]),
                       __half_as_ushort(l[2]), __half_as_ushort(l[3]) };
        size_t o = (size_t)(r0 + r) * 1024 + c0 + c;
        *reinterpret_cast<ushort4*>(Hb + o) = Hp;
        *reinterpret_cast<ushort4*>(Lb + o) = Lp;
    }
    __half* HTb = HT + (size_t)b * 1024 * 2048;
#pragma unroll
    for (int k = 0; k < 4; k++) {
        int id = k * 1024 + t * 4;
        int c = id >> 6, r = id & 63;
        __half h[4];
#pragma unroll
        for (int q = 0; q < 4; q++) h[q] = __float2half_rn(sm[r + q][c]);
        ushort4 Hp = { __half_as_ushort(h[0]), __half_as_ushort(h[1]),
                       __half_as_ushort(h[2]), __half_as_ushort(h[3]) };
        size_t o = (size_t)(c0 + c) * 2048 + r0 + r;
        *reinterpret_cast<ushort4*>(HTb + o) = Hp;
    }
}

// ============================ fused row softmax (compact) =========================
__global__ void row_softmax_kernel() {
    const int b = blockIdx.y;
    const int row = blockIdx.x;
    if (row >= c_pad(g_cntXp[b])) return;
    const int nYp = c_pad(g_cntYp[b]);
    const float* sp = g_s + (size_t)b * 2048 * 2048 + (size_t)row * 2048;
    const int t = threadIdx.x;
    const bool act = (t * 8) < nYp;
    float v[8];
    if (act) {
        *reinterpret_cast<float4*>(&v[0]) = *reinterpret_cast<const float4*>(sp + t * 8);
        *reinterpret_cast<float4*>(&v[4]) = *reinterpret_cast<const float4*>(sp + t * 8 + 4);
    } else {
#pragma unroll
        for (int r = 0; r < 8; r++) v[r] = NEGV;
    }
    float m = v[0];
#pragma unroll
    for (int r = 1; r < 8; r++) m = fmaxf(m, v[r]);
    __shared__ float red[256];
    red[t] = m; __syncthreads();
    for (int s = 128; s > 0; s >>= 1) { if (t < s) red[t] = fmaxf(red[t], red[t + s]); __syncthreads(); }
    const float rm = red[0]; __syncthreads();
    float p[8], sum = 0.f;
#pragma unroll
    for (int r = 0; r < 8; r++) { p[r] = __expf(v[r] - rm); sum += p[r]; }
    red[t] = sum; __syncthreads();
    for (int s = 128; s > 0; s >>= 1) { if (t < s) red[t] += red[t + s]; __syncthreads(); }
    const float ri = (red[0] > 0.f) ? 1.0f / red[0] : 0.f;
    if (!act) return;
    size_t o = (size_t)b * 2048 * 2048 + (size_t)row * 2048 + t * 8;
#pragma unroll
    for (int g = 0; g < 2; g++) {
        __half h[4], l[4];
#pragma unroll
        for (int q = 0; q < 4; q++) split2h(p[g * 4 + q] * ri, h[q], l[q]);
        ushort4 Hp = { __half_as_ushort(h[0]), __half_as_ushort(h[1]),
                       __half_as_ushort(h[2]), __half_as_ushort(h[3]) };
        ushort4 Lp = { __half_as_ushort(l[0]), __half_as_ushort(l[1]),
                       __half_as_ushort(l[2]), __half_as_ushort(l[3]) };
        *reinterpret_cast<ushort4*>(g_Phi + o + g * 4) = Hp;
        *reinterpret_cast<ushort4*>(g_Plo + o + g * 4) = Lp;
    }
}

// ============== fused col softmax: stats + exp + transpose in ONE kernel ==========
__global__ void colsoft_kernel() {
    const int b = blockIdx.y;
    const int j0 = blockIdx.x * 32;
    const int nYp = c_pad(g_cntYp[b]);
    if (j0 >= nYp) return;
    const int nXp = c_pad(g_cntXp[b]);
    const int tx = threadIdx.x, ty = threadIdx.y;
    const int j = j0 + tx;
    const float* S = g_s + (size_t)b * 2048 * 2048;

    float m = -3e38f;
    for (int i = ty; i < nXp; i += 8) m = fmaxf(m, S[(size_t)i * 2048 + j]);
    __shared__ float red[8][32];
    red[ty][tx] = m; __syncthreads();
    if (ty == 0) {
        float mm = red[0][tx];
#pragma unroll
        for (int r = 1; r < 8; r++) mm = fmaxf(mm, red[r][tx]);
        red[0][tx] = mm;
    }
    __syncthreads();
    const float cm = red[0][tx]; __syncthreads();
    float sum = 0.f;
    for (int i = ty; i < nXp; i += 8) sum += __expf(S[(size_t)i * 2048 + j] - cm);
    red[ty][tx] = sum; __syncthreads();
    if (ty == 0) {
        float ss = red[0][tx];
#pragma unroll
        for (int r = 1; r < 8; r++) ss += red[r][tx];
        red[0][tx] = ss;
    }
    __syncthreads();
    const float sv = red[0][tx];
    const float ci = (sv > 0.f) ? 1.0f / sv : 0.f;
    __syncthreads();

    __shared__ float sm[32][33];
    for (int i0 = 0; i0 < nXp; i0 += 32) {
#pragma unroll
        for (int k = 0; k < 4; k++) {
            int i = ty * 4 + k;
            float v = S[(size_t)(i0 + i) * 2048 + j];
            sm[tx][i] = __expf(v - cm) * ci;
        }
        __syncthreads();
#pragma unroll
        for (int k = 0; k < 4; k++) {
            int jj = ty * 4 + k;
            float v = sm[jj][tx];
            __half h, l; split2h(v, h, l);
            size_t o = (size_t)b * 2048 * 2048 + (size_t)(j0 + jj) * 2048 + i0 + tx;
            g_Pchi[o] = h; g_Pclo[o] = l;
        }
        __syncthreads();
    }
}

// ============================ mean + fill kernels (merged) ========================
__global__ void mean_kernel(const float* __restrict__ x, const float* __restrict__ y) {
    const int zz = blockIdx.y;
    const int b = zz & 15;
    const float* src = (zz < 16) ? y : x;
    float* dst = (zz < 16) ? g_meanY : g_meanX;
    const int d = blockIdx.x * 256 + threadIdx.x;
    const float* S = src + (size_t)b * 2048 * 1024 + d;
    float s0 = 0, s1 = 0, s2 = 0, s3 = 0;
    for (int i = 0; i < 2048; i += 4) {
        s0 += S[(size_t)i * 1024];
        s1 += S[(size_t)(i + 1) * 1024];
        s2 += S[(size_t)(i + 2) * 1024];
        s3 += S[(size_t)(i + 3) * 1024];
    }
    dst[b * 1024 + d] = (s0 + s1 + s2 + s3) * (1.0f / 2048.0f);
}

__global__ void mean_fill_kernel(const void* __restrict__ xm, const void* __restrict__ ym,
                                 float* __restrict__ out) {
    const int zz = blockIdx.y;
    const int b = zz & 15;
    const void* mask = (zz < 16) ? xm : ym;
    const float* mean = (zz < 16) ? g_meanY : g_meanX;
    float* dst = out + ((zz < 16) ? 0 : 33554432);
    const int i = blockIdx.x;
    if (!mask_at(mask, b * 2048 + i, g_mask_mode)) return;
    const int t = threadIdx.x;
    float4 v = *reinterpret_cast<const float4*>(mean + b * 1024 + t * 4);
    *reinterpret_cast<float4*>(dst + (size_t)b * 2048 * 1024 + (size_t)i * 1024 + t * 4) = v;
}

// ============ HMMA split GEMM (proj 3-term / score 3-term), K32, 3-stage ==========
__global__ __launch_bounds__(256, 2)
void gemm_hmma_kernel(int which, float* __restrict__ Cout)
{
    const int zz = blockIdx.z;
    const int sel = (which == 2) ? 0 : (zz >> 4);
    const int b = (which == 2) ? zz : (zz & 15);
    const int m0 = blockIdx.y * 128, n0 = blockIdx.x * 128;

    const __half *Ah, *Al, *Bh, *Bl;
    __half *Chi = nullptr, *Clo = nullptr;
    float* C = Cout;
    int lda, ldb, K, ldc, mode;
    int Mlim, Nlim = 1 << 30;
    int cRow = 0, cCol = 0;
    size_t sAb, sBb, cOff;

    if (which == 0) {
        if (sel == 0) { Ah = g_xhi; Al = g_xlo; Bh = g_wxhi; Bl = g_wxlo;
                        Mlim = c_pad(g_cntXp[b]); Chi = g_pxhi; Clo = g_pxlo; }
        else          { Ah = g_yhi; Al = g_ylo; Bh = g_wyhi; Bl = g_wylo;
                        Mlim = c_pad(g_cntYp[b]); Chi = g_pyhi; Clo = g_pylo; }
        lda = 1024; ldb = 1024; K = 1024; ldc = 1024; mode = 0;
        sAb = (size_t)2048 * 1024; sBb = 0; cOff = (size_t)b * 2048 * 1024;
    } else {
        Ah = g_pxhi; Al = g_pxlo; Bh = g_pyhi; Bl = g_pylo;
        lda = 1024; ldb = 1024; K = 1024; ldc = 2048; mode = 1;
        Mlim = c_pad(g_cntXp[b]); Nlim = c_pad(g_cntYp[b]);
        cRow = c_cnt(g_cntX[b]); cCol = c_cnt(g_cntY[b]);
        C = g_s; sAb = (size_t)2048 * 1024; sBb = (size_t)2048 * 1024;
        cOff = (size_t)b * 2048 * 2048;
    }
    if (m0 >= Mlim || n0 >= Nlim) return;

    extern __shared__ __align__(16) char smem_raw[];
    const uint32_t sb = smem_u32(smem_raw);
    const int tid = threadIdx.x, wid = tid >> 5, lane = tid & 31;
    const int warp_m = wid & 3, warp_n = wid >> 2;

    const __half* tp[4] = {
        Ah + (size_t)b * sAb + (size_t)m0 * lda,
        Al + (size_t)b * sAb + (size_t)m0 * lda,
        Bh + (size_t)b * sBb + (size_t)n0 * ldb,
        Bl + (size_t)b * sBb + (size_t)n0 * ldb
    };

    float acc[2][8][4];
#pragma unroll
    for (int i = 0; i < 2; i++)
#pragma unroll
        for (int j = 0; j < 8; j++)
#pragma unroll
            for (int q = 0; q < 4; q++) acc[i][j][q] = 0.0f;

    const int rowA = warp_m * 32 + (lane & 7) + ((lane >> 3) & 1) * 8;
    const int cA = (rowA >> 1) & 3;
    const uint32_t aoff = (uint32_t)rowA * 64 + (uint32_t)((((lane >> 4) & 1) ^ (cA & 1)) * 16);
    const uint32_t sxA = (uint32_t)(cA >> 1);
    const int rowB = warp_n * 64 + (lane & 7) + ((lane >> 4) & 1) * 8;
    const int cB = (rowB >> 1) & 3;
    const uint32_t boff = (uint32_t)rowB * 64 + (uint32_t)((((lane >> 3) & 1) ^ (cB & 1)) * 16);
    const uint32_t sxB = (uint32_t)(cB >> 1);

    const int NC = K >> 5;

    auto load_chunk = [&](int ch, int buf) {
#pragma unroll
        for (int i = 0; i < 8; i++) {
            const int o = i >> 1;
            const int idx = ((i & 1) << 8) + tid;
            const int row = idx >> 2, gr = idx & 3;
            const __half* src = tp[o] + (size_t)row * (o < 2 ? lda : ldb) + ch * 32 + gr * 8;
            const uint32_t dst = sb + (uint32_t)buf * 32768 + (uint32_t)o * 8192
                               + (uint32_t)row * 64 + (uint32_t)((gr ^ ((row >> 1) & 3)) * 16);
            asm volatile("cp.async.cg.shared.global [%0], [%1], 16;" :: "r"(dst), "l"(src));
        }
        asm volatile("cp.async.commit_group;");
    };

    load_chunk(0, 0);
    load_chunk(1, 1);
    int cbuf = 0, pbuf = 2;
    for (int ch = 0; ch < NC; ch++) {
        __syncthreads();
        if (ch + 2 < NC) {
            load_chunk(ch + 2, pbuf);
            asm volatile("cp.async.wait_group 2;" ::: "memory");
        } else if (ch + 1 < NC) {
            asm volatile("cp.async.wait_group 1;" ::: "memory");
        } else {
            asm volatile("cp.async.wait_group 0;" ::: "memory");
        }
        __syncthreads();
        const uint32_t base = sb + (uint32_t)cbuf * 32768;
        if (++cbuf == 3) cbuf = 0;
        if (++pbuf == 3) pbuf = 0;
#pragma unroll
        for (int s = 0; s < 2; s++) {
            const uint32_t sA = ((uint32_t)s ^ sxA) << 5;
            const uint32_t sB = ((uint32_t)s ^ sxB) << 5;
            uint32_t a[2][2][4];
#pragma unroll
            for (int mf = 0; mf < 2; mf++) {
                LDSM4(a[mf][0], base + aoff + mf * 1024 + sA);
                LDSM4(a[mf][1], base + 8192 + aoff + mf * 1024 + sA);
            }
            uint32_t bh[2][4], bl[2][4];
            LDSM4(bh[0], base + 16384 + boff + sB);
            LDSM4(bl[0], base + 24576 + boff + sB);
#pragma unroll
            for (int np = 0; np < 4; np++) {
                const int cur = np & 1;
                if (np < 3) {
                    LDSM4(bh[cur ^ 1], base + 16384 + boff + (np + 1) * 1024 + sB);
                    LDSM4(bl[cur ^ 1], base + 24576 + boff + (np + 1) * 1024 + sB);
                }
#pragma unroll
                for (int mf = 0; mf < 2; mf++) {
#pragma unroll
                    for (int h = 0; h < 2; h++) {
                        const int nf = np * 2 + h;
                        MMA_F16(acc[mf][nf], a[mf][0], bh[cur][2 * h], bh[cur][2 * h + 1]);
                        MMA_F16(acc[mf][nf], a[mf][0], bl[cur][2 * h], bl[cur][2 * h + 1]);
                        MMA_F16(acc[mf][nf], a[mf][1], bh[cur][2 * h], bh[cur][2 * h + 1]);
                    }
                }
            }
        }
    }
    asm volatile("cp.async.wait_group 0;" ::: "memory");

    const int rg = m0 + warp_m * 32 + (lane >> 2);
    const int cg = n0 + warp_n * 64 + (lane & 3) * 2;

    if (mode == 0) {
        __half* CH = Chi + cOff;
        __half* CL = Clo + cOff;
#pragma unroll
        for (int mf = 0; mf < 2; mf++) {
#pragma unroll
            for (int nf = 0; nf < 8; nf++) {
                const int R = rg + mf * 16;
                const int C0 = cg + nf * 8;
                float r0 = fmaxf(acc[mf][nf][0], 0.f), r1 = fmaxf(acc[mf][nf][1], 0.f);
                float r2 = fmaxf(acc[mf][nf][2], 0.f), r3 = fmaxf(acc[mf][nf][3], 0.f);
                __half h0, l0, h1, l1, h2, l2, h3, l3;
                split2h(r0, h0, l0); split2h(r1, h1, l1);
                split2h(r2, h2, l2); split2h(r3, h3, l3);
                uint32_t hp0 = (uint32_t)__half_as_ushort(h0) | ((uint32_t)__half_as_ushort(h1) << 16);
                uint32_t lp0 = (uint32_t)__half_as_ushort(l0) | ((uint32_t)__half_as_ushort(l1) << 16);
                uint32_t hp1 = (uint32_t)__half_as_ushort(h2) | ((uint32_t)__half_as_ushort(h3) << 16);
                uint32_t lp1 = (uint32_t)__half_as_ushort(l2) | ((uint32_t)__half_as_ushort(l3) << 16);
                *reinterpret_cast<uint32_t*>(CH + (size_t)R * ldc + C0) = hp0;
                *reinterpret_cast<uint32_t*>(CL + (size_t)R * ldc + C0) = lp0;
                *reinterpret_cast<uint32_t*>(CH + (size_t)(R + 8) * ldc + C0) = hp1;
                *reinterpret_cast<uint32_t*>(CL + (size_t)(R + 8) * ldc + C0) = lp1;
            }
        }
    } else {
        float* Co = C + cOff;
#pragma unroll
        for (int mf = 0; mf < 2; mf++) {
#pragma unroll
            for (int nf = 0; nf < 8; nf++) {
                const int R0 = rg + mf * 16, R1 = R0 + 8;
                const int C0 = cg + nf * 8;
                const bool c0v = C0 < cCol, c1v = (C0 + 1) < cCol;
                const bool r0v = R0 < cRow, r1v = R1 < cRow;
                float2 w0 = { (r0v && c0v) ? acc[mf][nf][0] : NEGV,
                              (r0v && c1v) ? acc[mf][nf][1] : NEGV };
                float2 w1 = { (r1v && c0v) ? acc[mf][nf][2] : NEGV,
                              (r1v && c1v) ? acc[mf][nf][3] : NEGV };
                *reinterpret_cast<float2*>(Co + (size_t)R0 * ldc + C0) = w0;
                *reinterpret_cast<float2*>(Co + (size_t)R1 * ldc + C0) = w1;
            }
        }
    }
}

// ======= attn GEMM (2-term): K-chunk 64, 2-stage, 128B-row swizzle, occ 2 =========
// z<16: y_h = P @ yT ; z>=16: x_h = Pc @ xT. All strides compile-time.
__global__ __launch_bounds__(256, 2)
void attn_hmma_kernel(float* __restrict__ Cout)
{
    const int zz = blockIdx.z;
    const int sel = zz >> 4;
    const int b = zz & 15;
    const int m0 = blockIdx.y * 128, n0 = blockIdx.x * 128;

    const __half *Ah, *Al, *Bh;
    int Mlim, K, cRow;
    const int* scat;
    size_t cOff;
    if (sel == 0) {
        Ah = g_Phi; Al = g_Plo; Bh = g_yThi;
        Mlim = c_pad(g_cntXp[b]); K = c_pad(g_cntYp[b]);
        cRow = c_cnt(g_cntX[b]); scat = g_idxX + b * 2048;
        cOff = (size_t)b * 2048 * 1024;
    } else {
        Ah = g_Pchi; Al = g_Pclo; Bh = g_xThi;
        Mlim = c_pad(g_cntYp[b]); K = c_pad(g_cntXp[b]);
        cRow = c_cnt(g_cntY[b]); scat = g_idxY + b * 2048;
        cOff = (size_t)33554432 + (size_t)b * 2048 * 1024;
    }
    if (m0 >= Mlim) return;

    extern __shared__ __align__(16) char smem_raw[];
    const uint32_t sb = smem_u32(smem_raw);
    const int tid = threadIdx.x, wid = tid >> 5, lane = tid & 31;
    const int warp_m = wid & 3, warp_n = wid >> 2;

    const __half* tp[3] = {
        Ah + (size_t)b * 2048 * 2048 + (size_t)m0 * 2048,
        Al + (size_t)b * 2048 * 2048 + (size_t)m0 * 2048,
        Bh + (size_t)b * 1024 * 2048 + (size_t)n0 * 2048
    };

    float acc[2][8][4];
#pragma unroll
    for (int i = 0; i < 2; i++)
#pragma unroll
        for (int j = 0; j < 8; j++)
#pragma unroll
            for (int q = 0; q < 4; q++) acc[i][j][q] = 0.0f;

    // per-lane constants; swizzle XOR reduces to lane&7 for both operands
    const int x7 = lane & 7;
    const uint32_t aoff = (uint32_t)(warp_m * 32 + (lane & 15)) * 128;
    const int hlA = (lane >> 4) & 1;
    const uint32_t boff = (uint32_t)(warp_n * 64 + (lane & 7) + ((lane >> 4) & 1) * 8) * 128;
    const int hlB = (lane >> 3) & 1;
    uint32_t axo[4], bxo[4];
#pragma unroll
    for (int s = 0; s < 4; s++) {
        axo[s] = (uint32_t)(((s * 2 + hlA) ^ x7) * 16);
        bxo[s] = (uint32_t)(((s * 2 + hlB) ^ x7) * 16);
    }

    const int NC = K >> 6;     // K multiple of 128 -> NC >= 2

    auto load_chunk = [&](int ch, int buf) {
#pragma unroll
        for (int i = 0; i < 12; i++) {
            const int o = i >> 2;                       // compile-time per i
            const int row = ((i & 3) * 256 + tid) >> 3; // 0..127
            const int gr = tid & 7;
            const __half* src = tp[o] + (size_t)row * 2048 + ch * 64 + gr * 8;
            const uint32_t dst = sb + (uint32_t)buf * 49152 + (uint32_t)o * 16384
                               + (uint32_t)row * 128 + (uint32_t)((gr ^ (row & 7)) * 16);
            asm volatile("cp.async.cg.shared.global [%0], [%1], 16;" :: "r"(dst), "l"(src));
        }
        asm volatile("cp.async.commit_group;");
    };

    load_chunk(0, 0);
    for (int ch = 0; ch < NC; ch++) {
        __syncthreads();                           // compute(ch-1) done -> buf (ch+1)&1 free
        if (ch + 1 < NC) {
            load_chunk(ch + 1, (ch + 1) & 1);
            asm volatile("cp.async.wait_group 1;" ::: "memory");   // chunk ch landed
        } else {
            asm volatile("cp.async.wait_group 0;" ::: "memory");
        }
        __syncthreads();                           // publish ch
        const uint32_t base = sb + (uint32_t)(ch & 1) * 49152;
        const uint32_t aB0 = base + aoff;
        const uint32_t aB1 = base + 16384 + aoff;
        const uint32_t bB  = base + 32768 + boff;
#pragma unroll
        for (int s = 0; s < 4; s++) {
            uint32_t a[2][2][4];
#pragma unroll
            for (int mf = 0; mf < 2; mf++) {
                LDSM4(a[mf][0], aB0 + mf * 2048 + axo[s]);
                LDSM4(a[mf][1], aB1 + mf * 2048 + axo[s]);
            }
            uint32_t bh[2][4];
            LDSM4(bh[0], bB + bxo[s]);
#pragma unroll
            for (int np = 0; np < 4; np++) {
                const int cur = np & 1;
                if (np < 3) LDSM4(bh[cur ^ 1], bB + (np + 1) * 2048 + bxo[s]);
#pragma unroll
                for (int mf = 0; mf < 2; mf++) {
#pragma unroll
                    for (int h = 0; h < 2; h++) {
                        const int nf = np * 2 + h;
                        MMA_F16(acc[mf][nf], a[mf][0], bh[cur][2 * h], bh[cur][2 * h + 1]);
                        MMA_F16(acc[mf][nf], a[mf][1], bh[cur][2 * h], bh[cur][2 * h + 1]);
                    }
                }
            }
        }
    }
    asm volatile("cp.async.wait_group 0;" ::: "memory");

    // scatter epilogue
    const int rg = m0 + warp_m * 32 + (lane >> 2);
    const int cg = n0 + warp_n * 64 + (lane & 3) * 2;
    float* Co = Cout + cOff;
    int gr2[2][2];
#pragma unroll
    for (int mf = 0; mf < 2; mf++)
#pragma unroll
        for (int h = 0; h < 2; h++) {
            const int R = rg + mf * 16 + h * 8;
            gr2[mf][h] = (R < cRow) ? c_idx(scat[R]) : -1;
        }
#pragma unroll
    for (int mf = 0; mf < 2; mf++) {
#pragma unroll
        for (int nf = 0; nf < 8; nf++) {
            const int C0 = cg + nf * 8;
            if (gr2[mf][0] >= 0) {
                float2 w = { acc[mf][nf][0], acc[mf][nf][1] };
                *reinterpret_cast<float2*>(Co + (size_t)gr2[mf][0] * 1024 + C0) = w;
            }
            if (gr2[mf][1] >= 0) {
                float2 w = { acc[mf][nf][2], acc[mf][nf][3] };
                *reinterpret_cast<float2*>(Co + (size_t)gr2[mf][1] * 1024 + C0) = w;
            }
        }
    }
}

// =================================================================================
extern "C" void kernel_launch(void* const* d_in, const int* in_sizes, int n_in,
                              void* d_out, int out_size)
{
    (void)in_sizes; (void)n_in; (void)out_size;
    const float* x  = (const float*)d_in[0];
    const float* y  = (const float*)d_in[1];
    const void*  xm = d_in[2];
    const void*  ym = d_in[3];
    const float* Wx = (const float*)d_in[4];
    const float* Wy = (const float*)d_in[5];
    float* out = (float*)d_out;

    static const int SMEM_GEMM = 98304;   // gemm: 3x32768 ; attn: 2x49152
    cudaFuncSetAttribute(gemm_hmma_kernel, cudaFuncAttributeMaxDynamicSharedMemorySize, SMEM_GEMM);
    cudaFuncSetAttribute(attn_hmma_kernel, cudaFuncAttributeMaxDynamicSharedMemorySize, SMEM_GEMM);

    // 0-2
    build_idx_kernel<<<32, 256>>>(xm, ym);
    gather_split_both_kernel<<<dim3(16, 32, 32), 256>>>(x, y);
    split_plain_kernel<<<2048, 256>>>(Wx, Wy);
    // 3: merged projection GEMM — ncu capture target
    gemm_hmma_kernel<<<dim3(8, 16, 32), 256, SMEM_GEMM>>>(0, nullptr);
    // score (3-term)
    gemm_hmma_kernel<<<dim3(16, 16, 16), 256, SMEM_GEMM>>>(2, nullptr);
    // softmax passes
    row_softmax_kernel<<<dim3(2048, 16), 256>>>();
    colsoft_kernel<<<dim3(64, 16), dim3(32, 8)>>>();
    // merged attention GEMMs: K64 2-stage kernel
    attn_hmma_kernel<<<dim3(8, 16, 32), 256, SMEM_GEMM>>>(out);
    // masked rows: exact means
    mean_kernel<<<dim3(4, 32), 256>>>(x, y);
    mean_fill_kernel<<<dim3(2048, 32), 256>>>(xm, ym, out);
}

// round 16
// speedup vs baseline: 1.6882x; 1.0689x over previous
#include <cuda_runtime.h>
#include <cuda_fp16.h>
#include <cstdint>

#define NEGV (-1e30f)

// ============================ scratch (device globals) ============================
static __device__ __align__(16) __half g_xhi[33554432], g_xlo[33554432];
static __device__ __align__(16) __half g_yhi[33554432], g_ylo[33554432];
static __device__ __align__(16) __half g_xThi[33554432], g_yThi[33554432];  // hi-only transposed
static __device__ __align__(16) __half g_wxhi[1048576], g_wxlo[1048576];
static __device__ __align__(16) __half g_wyhi[1048576], g_wylo[1048576];
static __device__ __align__(16) __half g_pxhi[33554432], g_pxlo[33554432];
static __device__ __align__(16) __half g_pyhi[33554432], g_pylo[33554432];
static __device__ __align__(16) float  g_s[67108864];
static __device__ __align__(16) __half g_Phi[67108864], g_Plo[67108864];
static __device__ __align__(16) __half g_Pchi[67108864], g_Pclo[67108864];
static __device__ __align__(16) float g_meanX[16384], g_meanY[16384];
static __device__ __align__(16) int   g_idxX[32768], g_idxY[32768];
static __device__ __align__(16) int   g_cntX[16], g_cntXp[16], g_cntY[16], g_cntYp[16];
static __device__ int   g_mask_mode;

// ============================ helpers =============================================
static __device__ __forceinline__ uint32_t smem_u32(const void* p) {
    uint32_t a;
    asm("{ .reg .u64 t; cvta.to.shared.u64 t, %1; cvt.u32.u64 %0, t; }" : "=r"(a) : "l"(p));
    return a;
}
__device__ __forceinline__ int c_cnt(int v)  { return v < 0 ? 0 : (v > 2048 ? 2048 : v); }
__device__ __forceinline__ int c_pad(int v)  {
    v &= ~127;
    return v < 128 ? 128 : (v > 2048 ? 2048 : v);
}
__device__ __forceinline__ int c_idx(int v)  { return v < 0 ? 0 : (v > 2047 ? 2047 : v); }

#define LDSM4(R, A)                                                                   \
    asm volatile("ldmatrix.sync.aligned.m8n8.x4.shared.b16 {%0,%1,%2,%3}, [%4];"      \
        : "=r"((R)[0]), "=r"((R)[1]), "=r"((R)[2]), "=r"((R)[3]) : "r"(A))

#define MMA_F16(C, A, B0, B1)                                                         \
    asm volatile("mma.sync.aligned.m16n8k16.row.col.f32.f16.f16.f32 "                 \
        "{%0,%1,%2,%3},{%4,%5,%6,%7},{%8,%9},{%0,%1,%2,%3};"                          \
        : "+f"((C)[0]), "+f"((C)[1]), "+f"((C)[2]), "+f"((C)[3])                      \
        : "r"((A)[0]), "r"((A)[1]), "r"((A)[2]), "r"((A)[3]), "r"(B0), "r"(B1))

__device__ __forceinline__ bool mask_at(const void* p, int idx, int mode) {
    if (mode == 0) return ((const unsigned char*)p)[idx] != 0;
    if (mode == 1) return ((const int*)p)[idx] != 0;
    return ((const float*)p)[idx] != 0.0f;
}

__device__ __forceinline__ void split2h(float v, __half& h, __half& l) {
    h = __float2half_rn(v);
    l = __float2half_rn(v - __half2float(h));
}

// ========= build unmasked index lists for BOTH masks (+ dtype detection) ==========
__global__ void build_idx_kernel(const void* __restrict__ xm, const void* __restrict__ ym) {
    const int whichm = blockIdx.x >> 4;
    const int b = blockIdx.x & 15;
    const void* mask = whichm ? ym : xm;
    const int t = threadIdx.x;                 // 256
    __shared__ int smode;
    __shared__ int scnt[256];
    if (t == 0) {
        const unsigned char* mb = (const unsigned char*)mask;
        unsigned a1 = 0, a3 = 0;
        for (int k = 0; k < 4096; k += 4) { a1 |= mb[k + 1]; a3 |= mb[k + 3]; }
        smode = a1 ? 0 : (a3 ? 2 : 1);
        if (b == 0 && whichm == 0) g_mask_mode = smode;
    }
    __syncthreads();
    const int mode = smode;
    const int base = b * 2048 + t * 8;
    int fl[8], c = 0;
#pragma unroll
    for (int r = 0; r < 8; r++) { fl[r] = mask_at(mask, base + r, mode) ? 0 : 1; c += fl[r]; }
    scnt[t] = c;
    __syncthreads();
    for (int ofs = 1; ofs < 256; ofs <<= 1) {
        int v = (t >= ofs) ? scnt[t - ofs] : 0;
        __syncthreads();
        scnt[t] += v;
        __syncthreads();
    }
    int pos = scnt[t] - c;
    int* idx = (whichm ? g_idxY : g_idxX) + b * 2048;
#pragma unroll
    for (int r = 0; r < 8; r++) if (fl[r]) idx[pos++] = t * 8 + r;
    __syncthreads();
    const int total = c_cnt(scnt[255]);
    for (int i = total + t; i < 2048; i += 256) idx[i] = 0;
    if (t == 255) {
        (whichm ? g_cntY : g_cntX)[b] = total;
        (whichm ? g_cntYp : g_cntXp)[b] = c_pad(total + 127);
    }
}

// ====================== weight split kernel (both weights) ========================
__global__ void split_plain_kernel(const float* __restrict__ Wx, const float* __restrict__ Wy) {
    const int blk = blockIdx.x;
    const int wsel = blk >> 10;
    const float* src = wsel ? Wy : Wx;
    __half* H = wsel ? g_wyhi : g_wxhi;
    __half* L = wsel ? g_wylo : g_wxlo;
    int i4 = ((blk & 1023) * 256 + threadIdx.x) * 4;
    float4 v = *reinterpret_cast<const float4*>(src + i4);
    __half h0, l0, h1, l1, h2, l2, h3, l3;
    split2h(v.x, h0, l0); split2h(v.y, h1, l1); split2h(v.z, h2, l2); split2h(v.w, h3, l3);
    ushort4 Hp = { __half_as_ushort(h0), __half_as_ushort(h1),
                   __half_as_ushort(h2), __half_as_ushort(h3) };
    ushort4 Lp = { __half_as_ushort(l0), __half_as_ushort(l1),
                   __half_as_ushort(l2), __half_as_ushort(l3) };
    *reinterpret_cast<ushort4*>(H + i4) = Hp;
    *reinterpret_cast<ushort4*>(L + i4) = Lp;
}

// ====== gather + split + transpose for BOTH tensors (z<16 -> x, z>=16 -> y) =======
__global__ void gather_split_both_kernel(const float* __restrict__ x, const float* __restrict__ y) {
    const int zz = blockIdx.z;
    const int isx = (zz < 16) ? 1 : 0;
    const int b = zz & 15;
    const float* src = isx ? x : y;
    const int cnt  = c_cnt((isx ? g_cntX  : g_cntY )[b]);
    const int cntp = c_pad((isx ? g_cntXp : g_cntYp)[b]);
    const int r0 = blockIdx.y * 64;
    if (r0 >= cntp) return;
    const int c0 = blockIdx.x * 64;
    __half* H  = isx ? g_xhi  : g_yhi;
    __half* L  = isx ? g_xlo  : g_ylo;
    __half* HT = isx ? g_xThi : g_yThi;
    const int* ib = (isx ? g_idxX : g_idxY) + b * 2048;
    __shared__ float sm[64][65];
    const int t = threadIdx.x;
    const float* S = src + (size_t)b * 2048 * 1024;
#pragma unroll
    for (int k = 0; k < 16; k++) {
        int id = k * 256 + t;
        int r = id >> 6, c = id & 63;
        int gr = r0 + r;
        float v = 0.0f;
        if (gr < cnt) v = S[(size_t)c_idx(ib[gr]) * 1024 + c0 + c];
        sm[r][c] = v;
    }
    __syncthreads();
    __half* Hb = H + (size_t)b * 2048 * 1024;
    __half* Lb = L + (size_t)b * 2048 * 1024;
#pragma unroll
    for (int k = 0; k < 4; k++) {
        int id = k * 1024 + t * 4;
        int r = id >> 6, c = id & 63;
        __half h[4], l[4];
#pragma unroll
        for (int q = 0; q < 4; q++) split2h(sm[r][c + q], h[q], l[q]);
        ushort4 Hp = { __half_as_ushort(h[0]), __half_as_ushort(h[1]),
                       __half_as_ushort(h[2]), __half_as_ushort(h[3]) };
        ushort4 Lp = { __half_as_ushort(l[0]), __half_as_ushort(l[1]),
                       __half_as_ushort(l[2]), __half_as_ushort(l[3]) };
        size_t o = (size_t)(r0 + r) * 1024 + c0 + c;
        *reinterpret_cast<ushort4*>(Hb + o) = Hp;
        *reinterpret_cast<ushort4*>(Lb + o) = Lp;
    }
    __half* HTb = HT + (size_t)b * 1024 * 2048;
#pragma unroll
    for (int k = 0; k < 4; k++) {
        int id = k * 1024 + t * 4;
        int c = id >> 6, r = id & 63;
        __half h[4];
#pragma unroll
        for (int q = 0; q < 4; q++) h[q] = __float2half_rn(sm[r + q][c]);
        ushort4 Hp = { __half_as_ushort(h[0]), __half_as_ushort(h[1]),
                       __half_as_ushort(h[2]), __half_as_ushort(h[3]) };
        size_t o = (size_t)(c0 + c) * 2048 + r0 + r;
        *reinterpret_cast<ushort4*>(HTb + o) = Hp;
    }
}

// ============================ fused row softmax (compact) =========================
__global__ void row_softmax_kernel() {
    const int b = blockIdx.y;
    const int row = blockIdx.x;
    if (row >= c_pad(g_cntXp[b])) return;
    const int nYp = c_pad(g_cntYp[b]);
    const float* sp = g_s + (size_t)b * 2048 * 2048 + (size_t)row * 2048;
    const int t = threadIdx.x;
    const bool act = (t * 8) < nYp;
    float v[8];
    if (act) {
        *reinterpret_cast<float4*>(&v[0]) = *reinterpret_cast<const float4*>(sp + t * 8);
        *reinterpret_cast<float4*>(&v[4]) = *reinterpret_cast<const float4*>(sp + t * 8 + 4);
    } else {
#pragma unroll
        for (int r = 0; r < 8; r++) v[r] = NEGV;
    }
    float m = v[0];
#pragma unroll
    for (int r = 1; r < 8; r++) m = fmaxf(m, v[r]);
    __shared__ float red[256];
    red[t] = m; __syncthreads();
    for (int s = 128; s > 0; s >>= 1) { if (t < s) red[t] = fmaxf(red[t], red[t + s]); __syncthreads(); }
    const float rm = red[0]; __syncthreads();
    float p[8], sum = 0.f;
#pragma unroll
    for (int r = 0; r < 8; r++) { p[r] = __expf(v[r] - rm); sum += p[r]; }
    red[t] = sum; __syncthreads();
    for (int s = 128; s > 0; s >>= 1) { if (t < s) red[t] += red[t + s]; __syncthreads(); }
    const float ri = (red[0] > 0.f) ? 1.0f / red[0] : 0.f;
    if (!act) return;
    size_t o = (size_t)b * 2048 * 2048 + (size_t)row * 2048 + t * 8;
#pragma unroll
    for (int g = 0; g < 2; g++) {
        __half h[4], l[4];
#pragma unroll
        for (int q = 0; q < 4; q++) split2h(p[g * 4 + q] * ri, h[q], l[q]);
        ushort4 Hp = { __half_as_ushort(h[0]), __half_as_ushort(h[1]),
                       __half_as_ushort(h[2]), __half_as_ushort(h[3]) };
        ushort4 Lp = { __half_as_ushort(l[0]), __half_as_ushort(l[1]),
                       __half_as_ushort(l[2]), __half_as_ushort(l[3]) };
        *reinterpret_cast<ushort4*>(g_Phi + o + g * 4) = Hp;
        *reinterpret_cast<ushort4*>(g_Plo + o + g * 4) = Lp;
    }
}

// ============== fused col softmax: stats + exp + transpose in ONE kernel ==========
__global__ void colsoft_kernel() {
    const int b = blockIdx.y;
    const int j0 = blockIdx.x * 32;
    const int nYp = c_pad(g_cntYp[b]);
    if (j0 >= nYp) return;
    const int nXp = c_pad(g_cntXp[b]);
    const int tx = threadIdx.x, ty = threadIdx.y;
    const int j = j0 + tx;
    const float* S = g_s + (size_t)b * 2048 * 2048;

    float m = -3e38f;
    for (int i = ty; i < nXp; i += 8) m = fmaxf(m, S[(size_t)i * 2048 + j]);
    __shared__ float red[8][32];
    red[ty][tx] = m; __syncthreads();
    if (ty == 0) {
        float mm = red[0][tx];
#pragma unroll
        for (int r = 1; r < 8; r++) mm = fmaxf(mm, red[r][tx]);
        red[0][tx] = mm;
    }
    __syncthreads();
    const float cm = red[0][tx]; __syncthreads();
    float sum = 0.f;
    for (int i = ty; i < nXp; i += 8) sum += __expf(S[(size_t)i * 2048 + j] - cm);
    red[ty][tx] = sum; __syncthreads();
    if (ty == 0) {
        float ss = red[0][tx];
#pragma unroll
        for (int r = 1; r < 8; r++) ss += red[r][tx];
        red[0][tx] = ss;
    }
    __syncthreads();
    const float sv = red[0][tx];
    const float ci = (sv > 0.f) ? 1.0f / sv : 0.f;
    __syncthreads();

    __shared__ float sm[32][33];
    for (int i0 = 0; i0 < nXp; i0 += 32) {
#pragma unroll
        for (int k = 0; k < 4; k++) {
            int i = ty * 4 + k;
            float v = S[(size_t)(i0 + i) * 2048 + j];
            sm[tx][i] = __expf(v - cm) * ci;
        }
        __syncthreads();
#pragma unroll
        for (int k = 0; k < 4; k++) {
            int jj = ty * 4 + k;
            float v = sm[jj][tx];
            __half h, l; split2h(v, h, l);
            size_t o = (size_t)b * 2048 * 2048 + (size_t)(j0 + jj) * 2048 + i0 + tx;
            g_Pchi[o] = h; g_Pclo[o] = l;
        }
        __syncthreads();
    }
}

// ============================ mean + fill kernels (merged) ========================
__global__ void mean_kernel(const float* __restrict__ x, const float* __restrict__ y) {
    const int zz = blockIdx.y;
    const int b = zz & 15;
    const float* src = (zz < 16) ? y : x;
    float* dst = (zz < 16) ? g_meanY : g_meanX;
    const int d = blockIdx.x * 256 + threadIdx.x;
    const float* S = src + (size_t)b * 2048 * 1024 + d;
    float s0 = 0, s1 = 0, s2 = 0, s3 = 0;
    for (int i = 0; i < 2048; i += 4) {
        s0 += S[(size_t)i * 1024];
        s1 += S[(size_t)(i + 1) * 1024];
        s2 += S[(size_t)(i + 2) * 1024];
        s3 += S[(size_t)(i + 3) * 1024];
    }
    dst[b * 1024 + d] = (s0 + s1 + s2 + s3) * (1.0f / 2048.0f);
}

__global__ void mean_fill_kernel(const void* __restrict__ xm, const void* __restrict__ ym,
                                 float* __restrict__ out) {
    const int zz = blockIdx.y;
    const int b = zz & 15;
    const void* mask = (zz < 16) ? xm : ym;
    const float* mean = (zz < 16) ? g_meanY : g_meanX;
    float* dst = out + ((zz < 16) ? 0 : 33554432);
    const int i = blockIdx.x;
    if (!mask_at(mask, b * 2048 + i, g_mask_mode)) return;
    const int t = threadIdx.x;
    float4 v = *reinterpret_cast<const float4*>(mean + b * 1024 + t * 4);
    *reinterpret_cast<float4*>(dst + (size_t)b * 2048 * 1024 + (size_t)i * 1024 + t * 4) = v;
}

// ===== proj/score GEMM (3-term): M64 N128 K-chunk 64, 2-stage, occ 2 ==============
// which: 0 = merged proj (z<16 x, z>=16 y), 2 = score
// Stage = Ahi 8K + Alo 8K + Bhi 16K + Blo 16K = 48KB; 2 stages = 96KB.
__global__ __launch_bounds__(256, 2)
void gemm64_hmma_kernel(int which, float* __restrict__ Cout)
{
    const int zz = blockIdx.z;
    const int sel = (which == 2) ? 0 : (zz >> 4);
    const int b = (which == 2) ? zz : (zz & 15);
    const int m0 = blockIdx.y * 64, n0 = blockIdx.x * 128;

    const __half *Ah, *Al, *Bh, *Bl;
    __half *Chi = nullptr, *Clo = nullptr;
    float* C = Cout;
    int ldc, mode;
    int Mlim, Nlim = 1 << 30;
    int cRow = 0, cCol = 0;
    size_t sBb, cOff;

    if (which == 0) {
        if (sel == 0) { Ah = g_xhi; Al = g_xlo; Bh = g_wxhi; Bl = g_wxlo;
                        Mlim = c_pad(g_cntXp[b]); Chi = g_pxhi; Clo = g_pxlo; }
        else          { Ah = g_yhi; Al = g_ylo; Bh = g_wyhi; Bl = g_wylo;
                        Mlim = c_pad(g_cntYp[b]); Chi = g_pyhi; Clo = g_pylo; }
        ldc = 1024; mode = 0;
        sBb = 0; cOff = (size_t)b * 2048 * 1024;
    } else {
        Ah = g_pxhi; Al = g_pxlo; Bh = g_pyhi; Bl = g_pylo;
        ldc = 2048; mode = 1;
        Mlim = c_pad(g_cntXp[b]); Nlim = c_pad(g_cntYp[b]);
        cRow = c_cnt(g_cntX[b]); cCol = c_cnt(g_cntY[b]);
        C = g_s; sBb = (size_t)2048 * 1024;
        cOff = (size_t)b * 2048 * 2048;
    }
    if (m0 >= Mlim || n0 >= Nlim) return;

    extern __shared__ __align__(16) char smem_raw[];
    const uint32_t sb = smem_u32(smem_raw);
    const int tid = threadIdx.x, wid = tid >> 5, lane = tid & 31;
    const int warp_m = wid & 1, warp_n = wid >> 1;       // 2 x 4

    const __half* tp[4] = {
        Ah + (size_t)b * 2048 * 1024 + (size_t)m0 * 1024,
        Al + (size_t)b * 2048 * 1024 + (size_t)m0 * 1024,
        Bh + (size_t)b * sBb + (size_t)n0 * 1024,
        Bl + (size_t)b * sBb + (size_t)n0 * 1024
    };

    float acc[2][4][4];
#pragma unroll
    for (int i = 0; i < 2; i++)
#pragma unroll
        for (int j = 0; j < 4; j++)
#pragma unroll
            for (int q = 0; q < 4; q++) acc[i][j][q] = 0.0f;

    // per-lane ldmatrix constants (128B rows, swizzle XOR = lane&7)
    const int x7 = lane & 7;
    const uint32_t aoff = (uint32_t)(warp_m * 32 + (lane & 15)) * 128;
    const int hlA = (lane >> 4) & 1;
    const uint32_t boff = (uint32_t)(warp_n * 32 + (lane & 7) + ((lane >> 4) & 1) * 8) * 128;
    const int hlB = (lane >> 3) & 1;
    uint32_t axo[4], bxo[4];
#pragma unroll
    for (int s = 0; s < 4; s++) {
        axo[s] = (uint32_t)(((s * 2 + hlA) ^ x7) * 16);
        bxo[s] = (uint32_t)(((s * 2 + hlB) ^ x7) * 16);
    }

    const int NC = 16;   // K = 1024, chunk 64

    auto load_chunk = [&](int ch, int buf) {
#pragma unroll
        for (int i = 0; i < 12; i++) {
            // i 0-1: Ahi(64r), 2-3: Alo(64r), 4-7: Bhi(128r), 8-11: Blo(128r)
            const int o   = (i < 2) ? 0 : (i < 4) ? 1 : (i < 8) ? 2 : 3;
            const int sub = (i < 4) ? (i & 1) : (i & 3);
            const int idx = sub * 256 + tid;
            const int row = idx >> 3, gr = tid & 7;
            const __half* src = tp[o] + (size_t)row * 1024 + ch * 64 + gr * 8;
            const uint32_t tof = (o == 0) ? 0u : (o == 1) ? 8192u : (o == 2) ? 16384u : 32768u;
            const uint32_t dst = sb + (uint32_t)buf * 49152 + tof
                               + (uint32_t)row * 128 + (uint32_t)((gr ^ (row & 7)) * 16);
            asm volatile("cp.async.cg.shared.global [%0], [%1], 16;" :: "r"(dst), "l"(src));
        }
        asm volatile("cp.async.commit_group;");
    };

    load_chunk(0, 0);
    for (int ch = 0; ch < NC; ch++) {
        __syncthreads();                           // compute(ch-1) done -> buf (ch+1)&1 free
        if (ch + 1 < NC) {
            load_chunk(ch + 1, (ch + 1) & 1);
            asm volatile("cp.async.wait_group 1;" ::: "memory");
        } else {
            asm volatile("cp.async.wait_group 0;" ::: "memory");
        }
        __syncthreads();                           // publish ch
        const uint32_t base = sb + (uint32_t)(ch & 1) * 49152;
        const uint32_t aB0 = base + aoff;
        const uint32_t aB1 = base + 8192 + aoff;
        const uint32_t bBh = base + 16384 + boff;
        const uint32_t bBl = base + 32768 + boff;
#pragma unroll
        for (int s = 0; s < 4; s++) {
            uint32_t a[2][2][4];
#pragma unroll
            for (int mf = 0; mf < 2; mf++) {
                LDSM4(a[mf][0], aB0 + mf * 2048 + axo[s]);
                LDSM4(a[mf][1], aB1 + mf * 2048 + axo[s]);
            }
            uint32_t bh[2][4], bl[2][4];
            LDSM4(bh[0], bBh + bxo[s]);
            LDSM4(bl[0], bBl + bxo[s]);
#pragma unroll
            for (int np = 0; np < 2; np++) {
                const int cur = np & 1;
                if (np < 1) {
                    LDSM4(bh[cur ^ 1], bBh + 2048 + bxo[s]);
                    LDSM4(bl[cur ^ 1], bBl + 2048 + bxo[s]);
                }
#pragma unroll
                for (int mf = 0; mf < 2; mf++) {
#pragma unroll
                    for (int h = 0; h < 2; h++) {
                        const int nf = np * 2 + h;
                        MMA_F16(acc[mf][nf], a[mf][0], bh[cur][2 * h], bh[cur][2 * h + 1]);
                        MMA_F16(acc[mf][nf], a[mf][0], bl[cur][2 * h], bl[cur][2 * h + 1]);
                        MMA_F16(acc[mf][nf], a[mf][1], bh[cur][2 * h], bh[cur][2 * h + 1]);
                    }
                }
            }
        }
    }
    asm volatile("cp.async.wait_group 0;" ::: "memory");

    // ------------------------------ epilogue ------------------------------
    const int rg = m0 + warp_m * 32 + (lane >> 2);
    const int cg = n0 + warp_n * 32 + (lane & 3) * 2;

    if (mode == 0) {
        __half* CH = Chi + cOff;
        __half* CL = Clo + cOff;
#pragma unroll
        for (int mf = 0; mf < 2; mf++) {
#pragma unroll
            for (int nf = 0; nf < 4; nf++) {
                const int R = rg + mf * 16;
                const int C0 = cg + nf * 8;
                float r0 = fmaxf(acc[mf][nf][0], 0.f), r1 = fmaxf(acc[mf][nf][1], 0.f);
                float r2 = fmaxf(acc[mf][nf][2], 0.f), r3 = fmaxf(acc[mf][nf][3], 0.f);
                __half h0, l0, h1, l1, h2, l2, h3, l3;
                split2h(r0, h0, l0); split2h(r1, h1, l1);
                split2h(r2, h2, l2); split2h(r3, h3, l3);
                uint32_t hp0 = (uint32_t)__half_as_ushort(h0) | ((uint32_t)__half_as_ushort(h1) << 16);
                uint32_t lp0 = (uint32_t)__half_as_ushort(l0) | ((uint32_t)__half_as_ushort(l1) << 16);
                uint32_t hp1 = (uint32_t)__half_as_ushort(h2) | ((uint32_t)__half_as_ushort(h3) << 16);
                uint32_t lp1 = (uint32_t)__half_as_ushort(l2) | ((uint32_t)__half_as_ushort(l3) << 16);
                *reinterpret_cast<uint32_t*>(CH + (size_t)R * ldc + C0) = hp0;
                *reinterpret_cast<uint32_t*>(CL + (size_t)R * ldc + C0) = lp0;
                *reinterpret_cast<uint32_t*>(CH + (size_t)(R + 8) * ldc + C0) = hp1;
                *reinterpret_cast<uint32_t*>(CL + (size_t)(R + 8) * ldc + C0) = lp1;
            }
        }
    } else {
        float* Co = C + cOff;
#pragma unroll
        for (int mf = 0; mf < 2; mf++) {
#pragma unroll
            for (int nf = 0; nf < 4; nf++) {
                const int R0 = rg + mf * 16, R1 = R0 + 8;
                const int C0 = cg + nf * 8;
                const bool c0v = C0 < cCol, c1v = (C0 + 1) < cCol;
                const bool r0v = R0 < cRow, r1v = R1 < cRow;
                float2 w0 = { (r0v && c0v) ? acc[mf][nf][0] : NEGV,
                              (r0v && c1v) ? acc[mf][nf][1] : NEGV };
                float2 w1 = { (r1v && c0v) ? acc[mf][nf][2] : NEGV,
                              (r1v && c1v) ? acc[mf][nf][3] : NEGV };
                *reinterpret_cast<float2*>(Co + (size_t)R0 * ldc + C0) = w0;
                *reinterpret_cast<float2*>(Co + (size_t)R1 * ldc + C0) = w1;
            }
        }
    }
}

// ======= attn GEMM (2-term): K-chunk 64, 2-stage, 128B-row swizzle, occ 2 =========
__global__ __launch_bounds__(256, 2)
void attn_hmma_kernel(float* __restrict__ Cout)
{
    const int zz = blockIdx.z;
    const int sel = zz >> 4;
    const int b = zz & 15;
    const int m0 = blockIdx.y * 128, n0 = blockIdx.x * 128;

    const __half *Ah, *Al, *Bh;
    int Mlim, K, cRow;
    const int* scat;
    size_t cOff;
    if (sel == 0) {
        Ah = g_Phi; Al = g_Plo; Bh = g_yThi;
        Mlim = c_pad(g_cntXp[b]); K = c_pad(g_cntYp[b]);
        cRow = c_cnt(g_cntX[b]); scat = g_idxX + b * 2048;
        cOff = (size_t)b * 2048 * 1024;
    } else {
        Ah = g_Pchi; Al = g_Pclo; Bh = g_xThi;
        Mlim = c_pad(g_cntYp[b]); K = c_pad(g_cntXp[b]);
        cRow = c_cnt(g_cntY[b]); scat = g_idxY + b * 2048;
        cOff = (size_t)33554432 + (size_t)b * 2048 * 1024;
    }
    if (m0 >= Mlim) return;

    extern __shared__ __align__(16) char smem_raw[];
    const uint32_t sb = smem_u32(smem_raw);
    const int tid = threadIdx.x, wid = tid >> 5, lane = tid & 31;
    const int warp_m = wid & 3, warp_n = wid >> 2;

    const __half* tp[3] = {
        Ah + (size_t)b * 2048 * 2048 + (size_t)m0 * 2048,
        Al + (size_t)b * 2048 * 2048 + (size_t)m0 * 2048,
        Bh + (size_t)b * 1024 * 2048 + (size_t)n0 * 2048
    };

    float acc[2][8][4];
#pragma unroll
    for (int i = 0; i < 2; i++)
#pragma unroll
        for (int j = 0; j < 8; j++)
#pragma unroll
            for (int q = 0; q < 4; q++) acc[i][j][q] = 0.0f;

    const int x7 = lane & 7;
    const uint32_t aoff = (uint32_t)(warp_m * 32 + (lane & 15)) * 128;
    const int hlA = (lane >> 4) & 1;
    const uint32_t boff = (uint32_t)(warp_n * 64 + (lane & 7) + ((lane >> 4) & 1) * 8) * 128;
    const int hlB = (lane >> 3) & 1;
    uint32_t axo[4], bxo[4];
#pragma unroll
    for (int s = 0; s < 4; s++) {
        axo[s] = (uint32_t)(((s * 2 + hlA) ^ x7) * 16);
        bxo[s] = (uint32_t)(((s * 2 + hlB) ^ x7) * 16);
    }

    const int NC = K >> 6;

    auto load_chunk = [&](int ch, int buf) {
#pragma unroll
        for (int i = 0; i < 12; i++) {
            const int o = i >> 2;
            const int row = ((i & 3) * 256 + tid) >> 3;
            const int gr = tid & 7;
            const __half* src = tp[o] + (size_t)row * 2048 + ch * 64 + gr * 8;
            const uint32_t dst = sb + (uint32_t)buf * 49152 + (uint32_t)o * 16384
                               + (uint32_t)row * 128 + (uint32_t)((gr ^ (row & 7)) * 16);
            asm volatile("cp.async.cg.shared.global [%0], [%1], 16;" :: "r"(dst), "l"(src));
        }
        asm volatile("cp.async.commit_group;");
    };

    load_chunk(0, 0);
    for (int ch = 0; ch < NC; ch++) {
        __syncthreads();
        if (ch + 1 < NC) {
            load_chunk(ch + 1, (ch + 1) & 1);
            asm volatile("cp.async.wait_group 1;" ::: "memory");
        } else {
            asm volatile("cp.async.wait_group 0;" ::: "memory");
        }
        __syncthreads();
        const uint32_t base = sb + (uint32_t)(ch & 1) * 49152;
        const uint32_t aB0 = base + aoff;
        const uint32_t aB1 = base + 16384 + aoff;
        const uint32_t bB  = base + 32768 + boff;
#pragma unroll
        for (int s = 0; s < 4; s++) {
            uint32_t a[2][2][4];
#pragma unroll
            for (int mf = 0; mf < 2; mf++) {
                LDSM4(a[mf][0], aB0 + mf * 2048 + axo[s]);
                LDSM4(a[mf][1], aB1 + mf * 2048 + axo[s]);
            }
            uint32_t bh[2][4];
            LDSM4(bh[0], bB + bxo[s]);
#pragma unroll
            for (int np = 0; np < 4; np++) {
                const int cur = np & 1;
                if (np < 3) LDSM4(bh[cur ^ 1], bB + (np + 1) * 2048 + bxo[s]);
#pragma unroll
                for (int mf = 0; mf < 2; mf++) {
#pragma unroll
                    for (int h = 0; h < 2; h++) {
                        const int nf = np * 2 + h;
                        MMA_F16(acc[mf][nf], a[mf][0], bh[cur][2 * h], bh[cur][2 * h + 1]);
                        MMA_F16(acc[mf][nf], a[mf][1], bh[cur][2 * h], bh[cur][2 * h + 1]);
                    }
                }
            }
        }
    }
    asm volatile("cp.async.wait_group 0;" ::: "memory");

    const int rg = m0 + warp_m * 32 + (lane >> 2);
    const int cg = n0 + warp_n * 64 + (lane & 3) * 2;
    float* Co = Cout + cOff;
    int gr2[2][2];
#pragma unroll
    for (int mf = 0; mf < 2; mf++)
#pragma unroll
        for (int h = 0; h < 2; h++) {
            const int R = rg + mf * 16 + h * 8;
            gr2[mf][h] = (R < cRow) ? c_idx(scat[R]) : -1;
        }
#pragma unroll
    for (int mf = 0; mf < 2; mf++) {
#pragma unroll
        for (int nf = 0; nf < 8; nf++) {
            const int C0 = cg + nf * 8;
            if (gr2[mf][0] >= 0) {
                float2 w = { acc[mf][nf][0], acc[mf][nf][1] };
                *reinterpret_cast<float2*>(Co + (size_t)gr2[mf][0] * 1024 + C0) = w;
            }
            if (gr2[mf][1] >= 0) {
                float2 w = { acc[mf][nf][2], acc[mf][nf][3] };
                *reinterpret_cast<float2*>(Co + (size_t)gr2[mf][1] * 1024 + C0) = w;
            }
        }
    }
}

// =================================================================================
extern "C" void kernel_launch(void* const* d_in, const int* in_sizes, int n_in,
                              void* d_out, int out_size)
{
    (void)in_sizes; (void)n_in; (void)out_size;
    const float* x  = (const float*)d_in[0];
    const float* y  = (const float*)d_in[1];
    const void*  xm = d_in[2];
    const void*  ym = d_in[3];
    const float* Wx = (const float*)d_in[4];
    const float* Wy = (const float*)d_in[5];
    float* out = (float*)d_out;

    static const int SMEM_GEMM = 98304;   // 2 stages x 49152
    cudaFuncSetAttribute(gemm64_hmma_kernel, cudaFuncAttributeMaxDynamicSharedMemorySize, SMEM_GEMM);
    cudaFuncSetAttribute(attn_hmma_kernel, cudaFuncAttributeMaxDynamicSharedMemorySize, SMEM_GEMM);

    // 0-2
    build_idx_kernel<<<32, 256>>>(xm, ym);
    gather_split_both_kernel<<<dim3(16, 32, 32), 256>>>(x, y);
    split_plain_kernel<<<2048, 256>>>(Wx, Wy);
    // 3: merged projection GEMM (M64 K64) — ncu capture target
    gemm64_hmma_kernel<<<dim3(8, 32, 32), 256, SMEM_GEMM>>>(0, nullptr);
    // score (M64 K64, 3-term)
    gemm64_hmma_kernel<<<dim3(16, 32, 16), 256, SMEM_GEMM>>>(2, nullptr);
    // softmax passes
    row_softmax_kernel<<<dim3(2048, 16), 256>>>();
    colsoft_kernel<<<dim3(64, 16), dim3(32, 8)>>>();
    // merged attention GEMMs: K64 2-stage kernel
    attn_hmma_kernel<<<dim3(8, 16, 32), 256, SMEM_GEMM>>>(out);
    // masked rows: exact means
    mean_kernel<<<dim3(4, 32), 256>>>(x, y);
    mean_fill_kernel<<<dim3(2048, 32), 256>>>(xm, ym, out);
}

// round 17
// speedup vs baseline: 1.6909x; 1.0016x over previous
#include <cuda_runtime.h>
#include <cuda_fp16.h>
#include <cstdint>

#define NEGV (-1e30f)

// ============================ scratch (device globals) ============================
static __device__ __align__(16) __half g_xhi[33554432], g_xlo[33554432];
static __device__ __align__(16) __half g_yhi[33554432], g_ylo[33554432];
static __device__ __align__(16) __half g_xThi[33554432], g_yThi[33554432];  // hi-only transposed
static __device__ __align__(16) __half g_wxhi[1048576], g_wxlo[1048576];
static __device__ __align__(16) __half g_wyhi[1048576], g_wylo[1048576];
static __device__ __align__(16) __half g_pxhi[33554432], g_pxlo[33554432];
static __device__ __align__(16) __half g_pyhi[33554432], g_pylo[33554432];
static __device__ __align__(16) float  g_s[67108864];
static __device__ __align__(16) __half g_Phi[67108864], g_Plo[67108864];
static __device__ __align__(16) __half g_Pchi[67108864], g_Pclo[67108864];
static __device__ __align__(16) float g_meanX[16384], g_meanY[16384];
static __device__ __align__(16) int   g_idxX[32768], g_idxY[32768];
static __device__ __align__(16) int   g_cntX[16], g_cntXp[16], g_cntY[16], g_cntYp[16];
static __device__ int   g_mask_mode;

// ============================ helpers =============================================
static __device__ __forceinline__ uint32_t smem_u32(const void* p) {
    uint32_t a;
    asm("{ .reg .u64 t; cvta.to.shared.u64 t, %1; cvt.u32.u64 %0, t; }" : "=r"(a) : "l"(p));
    return a;
}
__device__ __forceinline__ int c_cnt(int v)  { return v < 0 ? 0 : (v > 2048 ? 2048 : v); }
__device__ __forceinline__ int c_pad(int v)  {
    v &= ~127;
    return v < 128 ? 128 : (v > 2048 ? 2048 : v);
}
__device__ __forceinline__ int c_idx(int v)  { return v < 0 ? 0 : (v > 2047 ? 2047 : v); }

#define LDSM4(R, A)                                                                   \
    asm volatile("ldmatrix.sync.aligned.m8n8.x4.shared.b16 {%0,%1,%2,%3}, [%4];"      \
        : "=r"((R)[0]), "=r"((R)[1]), "=r"((R)[2]), "=r"((R)[3]) : "r"(A))

#define MMA_F16(C, A, B0, B1)                                                         \
    asm volatile("mma.sync.aligned.m16n8k16.row.col.f32.f16.f16.f32 "                 \
        "{%0,%1,%2,%3},{%4,%5,%6,%7},{%8,%9},{%0,%1,%2,%3};"                          \
        : "+f"((C)[0]), "+f"((C)[1]), "+f"((C)[2]), "+f"((C)[3])                      \
        : "r"((A)[0]), "r"((A)[1]), "r"((A)[2]), "r"((A)[3]), "r"(B0), "r"(B1))

__device__ __forceinline__ bool mask_at(const void* p, int idx, int mode) {
    if (mode == 0) return ((const unsigned char*)p)[idx] != 0;
    if (mode == 1) return ((const int*)p)[idx] != 0;
    return ((const float*)p)[idx] != 0.0f;
}

__device__ __forceinline__ void split2h(float v, __half& h, __half& l) {
    h = __float2half_rn(v);
    l = __float2half_rn(v - __half2float(h));
}

// ========= build unmasked index lists for BOTH masks (+ dtype detection) ==========
__global__ void build_idx_kernel(const void* __restrict__ xm, const void* __restrict__ ym) {
    const int whichm = blockIdx.x >> 4;
    const int b = blockIdx.x & 15;
    const void* mask = whichm ? ym : xm;
    const int t = threadIdx.x;                 // 256
    __shared__ int smode;
    __shared__ int scnt[256];
    if (t == 0) {
        const unsigned char* mb = (const unsigned char*)mask;
        unsigned a1 = 0, a3 = 0;
        for (int k = 0; k < 4096; k += 4) { a1 |= mb[k + 1]; a3 |= mb[k + 3]; }
        smode = a1 ? 0 : (a3 ? 2 : 1);
        if (b == 0 && whichm == 0) g_mask_mode = smode;
    }
    __syncthreads();
    const int mode = smode;
    const int base = b * 2048 + t * 8;
    int fl[8], c = 0;
#pragma unroll
    for (int r = 0; r < 8; r++) { fl[r] = mask_at(mask, base + r, mode) ? 0 : 1; c += fl[r]; }
    scnt[t] = c;
    __syncthreads();
    for (int ofs = 1; ofs < 256; ofs <<= 1) {
        int v = (t >= ofs) ? scnt[t - ofs] : 0;
        __syncthreads();
        scnt[t] += v;
        __syncthreads();
    }
    int pos = scnt[t] - c;
    int* idx = (whichm ? g_idxY : g_idxX) + b * 2048;
#pragma unroll
    for (int r = 0; r < 8; r++) if (fl[r]) idx[pos++] = t * 8 + r;
    __syncthreads();
    const int total = c_cnt(scnt[255]);
    for (int i = total + t; i < 2048; i += 256) idx[i] = 0;
    if (t == 255) {
        (whichm ? g_cntY : g_cntX)[b] = total;
        (whichm ? g_cntYp : g_cntXp)[b] = c_pad(total + 127);
    }
}

// ====================== weight split kernel (both weights) ========================
__global__ void split_plain_kernel(const float* __restrict__ Wx, const float* __restrict__ Wy) {
    const int blk = blockIdx.x;
    const int wsel = blk >> 10;
    const float* src = wsel ? Wy : Wx;
    __half* H = wsel ? g_wyhi : g_wxhi;
    __half* L = wsel ? g_wylo : g_wxlo;
    int i4 = ((blk & 1023) * 256 + threadIdx.x) * 4;
    float4 v = *reinterpret_cast<const float4*>(src + i4);
    __half h0, l0, h1, l1, h2, l2, h3, l3;
    split2h(v.x, h0, l0); split2h(v.y, h1, l1); split2h(v.z, h2, l2); split2h(v.w, h3, l3);
    ushort4 Hp = { __half_as_ushort(h0), __half_as_ushort(h1),
                   __half_as_ushort(h2), __half_as_ushort(h3) };
    ushort4 Lp = { __half_as_ushort(l0), __half_as_ushort(l1),
                   __half_as_ushort(l2), __half_as_ushort(l3) };
    *reinterpret_cast<ushort4*>(H + i4) = Hp;
    *reinterpret_cast<ushort4*>(L + i4) = Lp;
}

// ====== gather + split + transpose for BOTH tensors (z<16 -> x, z>=16 -> y) =======
__global__ void gather_split_both_kernel(const float* __restrict__ x, const float* __restrict__ y) {
    const int zz = blockIdx.z;
    const int isx = (zz < 16) ? 1 : 0;
    const int b = zz & 15;
    const float* src = isx ? x : y;
    const int cnt  = c_cnt((isx ? g_cntX  : g_cntY )[b]);
    const int cntp = c_pad((isx ? g_cntXp : g_cntYp)[b]);
    const int r0 = blockIdx.y * 64;
    if (r0 >= cntp) return;
    const int c0 = blockIdx.x * 64;
    __half* H  = isx ? g_xhi  : g_yhi;
    __half* L  = isx ? g_xlo  : g_ylo;
    __half* HT = isx ? g_xThi : g_yThi;
    const int* ib = (isx ? g_idxX : g_idxY) + b * 2048;
    __shared__ float sm[64][65];
    const int t = threadIdx.x;
    const float* S = src + (size_t)b * 2048 * 1024;
#pragma unroll
    for (int k = 0; k < 16; k++) {
        int id = k * 256 + t;
        int r = id >> 6, c = id & 63;
        int gr = r0 + r;
        float v = 0.0f;
        if (gr < cnt) v = S[(size_t)c_idx(ib[gr]) * 1024 + c0 + c];
        sm[r][c] = v;
    }
    __syncthreads();
    __half* Hb = H + (size_t)b * 2048 * 1024;
    __half* Lb = L + (size_t)b * 2048 * 1024;
#pragma unroll
    for (int k = 0; k < 4; k++) {
        int id = k * 1024 + t * 4;
        int r = id >> 6, c = id & 63;
        __half h[4], l[4];
#pragma unroll
        for (int q = 0; q < 4; q++) split2h(sm[r][c + q], h[q], l[q]);
        ushort4 Hp = { __half_as_ushort(h[0]), __half_as_ushort(h[1]),
                       __half_as_ushort(h[2]), __half_as_ushort(h[3]) };
        ushort4 Lp = { __half_as_ushort(l[0]), __half_as_ushort(l[1]),
                       __half_as_ushort(l[2]), __half_as_ushort(l[3]) };
        size_t o = (size_t)(r0 + r) * 1024 + c0 + c;
        *reinterpret_cast<ushort4*>(Hb + o) = Hp;
        *reinterpret_cast<ushort4*>(Lb + o) = Lp;
    }
    __half* HTb = HT + (size_t)b * 1024 * 2048;
#pragma unroll
    for (int k = 0; k < 4; k++) {
        int id = k * 1024 + t * 4;
        int c = id >> 6, r = id & 63;
        __half h[4];
#pragma unroll
        for (int q = 0; q < 4; q++) h[q] = __float2half_rn(sm[r + q][c]);
        ushort4 Hp = { __half_as_ushort(h[0]), __half_as_ushort(h[1]),
                       __half_as_ushort(h[2]), __half_as_ushort(h[3]) };
        size_t o = (size_t)(c0 + c) * 2048 + r0 + r;
        *reinterpret_cast<ushort4*>(HTb + o) = Hp;
    }
}

// ============================ fused row softmax (compact) =========================
__global__ void row_softmax_kernel() {
    const int b = blockIdx.y;
    const int row = blockIdx.x;
    if (row >= c_pad(g_cntXp[b])) return;
    const int nYp = c_pad(g_cntYp[b]);
    const float* sp = g_s + (size_t)b * 2048 * 2048 + (size_t)row * 2048;
    const int t = threadIdx.x;
    const bool act = (t * 8) < nYp;
    float v[8];
    if (act) {
        *reinterpret_cast<float4*>(&v[0]) = *reinterpret_cast<const float4*>(sp + t * 8);
        *reinterpret_cast<float4*>(&v[4]) = *reinterpret_cast<const float4*>(sp + t * 8 + 4);
    } else {
#pragma unroll
        for (int r = 0; r < 8; r++) v[r] = NEGV;
    }
    float m = v[0];
#pragma unroll
    for (int r = 1; r < 8; r++) m = fmaxf(m, v[r]);
    __shared__ float red[256];
    red[t] = m; __syncthreads();
    for (int s = 128; s > 0; s >>= 1) { if (t < s) red[t] = fmaxf(red[t], red[t + s]); __syncthreads(); }
    const float rm = red[0]; __syncthreads();
    float p[8], sum = 0.f;
#pragma unroll
    for (int r = 0; r < 8; r++) { p[r] = __expf(v[r] - rm); sum += p[r]; }
    red[t] = sum; __syncthreads();
    for (int s = 128; s > 0; s >>= 1) { if (t < s) red[t] += red[t + s]; __syncthreads(); }
    const float ri = (red[0] > 0.f) ? 1.0f / red[0] : 0.f;
    if (!act) return;
    size_t o = (size_t)b * 2048 * 2048 + (size_t)row * 2048 + t * 8;
#pragma unroll
    for (int g = 0; g < 2; g++) {
        __half h[4], l[4];
#pragma unroll
        for (int q = 0; q < 4; q++) split2h(p[g * 4 + q] * ri, h[q], l[q]);
        ushort4 Hp = { __half_as_ushort(h[0]), __half_as_ushort(h[1]),
                       __half_as_ushort(h[2]), __half_as_ushort(h[3]) };
        ushort4 Lp = { __half_as_ushort(l[0]), __half_as_ushort(l[1]),
                       __half_as_ushort(l[2]), __half_as_ushort(l[3]) };
        *reinterpret_cast<ushort4*>(g_Phi + o + g * 4) = Hp;
        *reinterpret_cast<ushort4*>(g_Plo + o + g * 4) = Lp;
    }
}

// ============== fused col softmax: stats + exp + transpose in ONE kernel ==========
__global__ void colsoft_kernel() {
    const int b = blockIdx.y;
    const int j0 = blockIdx.x * 32;
    const int nYp = c_pad(g_cntYp[b]);
    if (j0 >= nYp) return;
    const int nXp = c_pad(g_cntXp[b]);
    const int tx = threadIdx.x, ty = threadIdx.y;
    const int j = j0 + tx;
    const float* S = g_s + (size_t)b * 2048 * 2048;

    float m = -3e38f;
    for (int i = ty; i < nXp; i += 8) m = fmaxf(m, S[(size_t)i * 2048 + j]);
    __shared__ float red[8][32];
    red[ty][tx] = m; __syncthreads();
    if (ty == 0) {
        float mm = red[0][tx];
#pragma unroll
        for (int r = 1; r < 8; r++) mm = fmaxf(mm, red[r][tx]);
        red[0][tx] = mm;
    }
    __syncthreads();
    const float cm = red[0][tx]; __syncthreads();
    float sum = 0.f;
    for (int i = ty; i < nXp; i += 8) sum += __expf(S[(size_t)i * 2048 + j] - cm);
    red[ty][tx] = sum; __syncthreads();
    if (ty == 0) {
        float ss = red[0][tx];
#pragma unroll
        for (int r = 1; r < 8; r++) ss += red[r][tx];
        red[0][tx] = ss;
    }
    __syncthreads();
    const float sv = red[0][tx];
    const float ci = (sv > 0.f) ? 1.0f / sv : 0.f;
    __syncthreads();

    __shared__ float sm[32][33];
    for (int i0 = 0; i0 < nXp; i0 += 32) {
#pragma unroll
        for (int k = 0; k < 4; k++) {
            int i = ty * 4 + k;
            float v = S[(size_t)(i0 + i) * 2048 + j];
            sm[tx][i] = __expf(v - cm) * ci;
        }
        __syncthreads();
#pragma unroll
        for (int k = 0; k < 4; k++) {
            int jj = ty * 4 + k;
            float v = sm[jj][tx];
            __half h, l; split2h(v, h, l);
            size_t o = (size_t)b * 2048 * 2048 + (size_t)(j0 + jj) * 2048 + i0 + tx;
            g_Pchi[o] = h; g_Pclo[o] = l;
        }
        __syncthreads();
    }
}

// ============================ mean + fill kernels (merged) ========================
__global__ void mean_kernel(const float* __restrict__ x, const float* __restrict__ y) {
    const int zz = blockIdx.y;
    const int b = zz & 15;
    const float* src = (zz < 16) ? y : x;
    float* dst = (zz < 16) ? g_meanY : g_meanX;
    const int d = blockIdx.x * 256 + threadIdx.x;
    const float* S = src + (size_t)b * 2048 * 1024 + d;
    float s0 = 0, s1 = 0, s2 = 0, s3 = 0;
    for (int i = 0; i < 2048; i += 4) {
        s0 += S[(size_t)i * 1024];
        s1 += S[(size_t)(i + 1) * 1024];
        s2 += S[(size_t)(i + 2) * 1024];
        s3 += S[(size_t)(i + 3) * 1024];
    }
    dst[b * 1024 + d] = (s0 + s1 + s2 + s3) * (1.0f / 2048.0f);
}

__global__ void mean_fill_kernel(const void* __restrict__ xm, const void* __restrict__ ym,
                                 float* __restrict__ out) {
    const int zz = blockIdx.y;
    const int b = zz & 15;
    const void* mask = (zz < 16) ? xm : ym;
    const float* mean = (zz < 16) ? g_meanY : g_meanX;
    float* dst = out + ((zz < 16) ? 0 : 33554432);
    const int i = blockIdx.x;
    if (!mask_at(mask, b * 2048 + i, g_mask_mode)) return;
    const int t = threadIdx.x;
    float4 v = *reinterpret_cast<const float4*>(mean + b * 1024 + t * 4);
    *reinterpret_cast<float4*>(dst + (size_t)b * 2048 * 1024 + (size_t)i * 1024 + t * 4) = v;
}

// ===== proj/score GEMM (3-term): M64 N128 K-chunk 64, 2-stage, occ 2 ==============
__global__ __launch_bounds__(256, 2)
void gemm64_hmma_kernel(int which, float* __restrict__ Cout)
{
    const int zz = blockIdx.z;
    const int sel = (which == 2) ? 0 : (zz >> 4);
    const int b = (which == 2) ? zz : (zz & 15);
    const int m0 = blockIdx.y * 64, n0 = blockIdx.x * 128;

    const __half *Ah, *Al, *Bh, *Bl;
    __half *Chi = nullptr, *Clo = nullptr;
    float* C = Cout;
    int ldc, mode;
    int Mlim, Nlim = 1 << 30;
    int cRow = 0, cCol = 0;
    size_t sBb, cOff;

    if (which == 0) {
        if (sel == 0) { Ah = g_xhi; Al = g_xlo; Bh = g_wxhi; Bl = g_wxlo;
                        Mlim = c_pad(g_cntXp[b]); Chi = g_pxhi; Clo = g_pxlo; }
        else          { Ah = g_yhi; Al = g_ylo; Bh = g_wyhi; Bl = g_wylo;
                        Mlim = c_pad(g_cntYp[b]); Chi = g_pyhi; Clo = g_pylo; }
        ldc = 1024; mode = 0;
        sBb = 0; cOff = (size_t)b * 2048 * 1024;
    } else {
        Ah = g_pxhi; Al = g_pxlo; Bh = g_pyhi; Bl = g_pylo;
        ldc = 2048; mode = 1;
        Mlim = c_pad(g_cntXp[b]); Nlim = c_pad(g_cntYp[b]);
        cRow = c_cnt(g_cntX[b]); cCol = c_cnt(g_cntY[b]);
        C = g_s; sBb = (size_t)2048 * 1024;
        cOff = (size_t)b * 2048 * 2048;
    }
    if (m0 >= Mlim || n0 >= Nlim) return;

    extern __shared__ __align__(16) char smem_raw[];
    const uint32_t sb = smem_u32(smem_raw);
    const int tid = threadIdx.x, wid = tid >> 5, lane = tid & 31;
    const int warp_m = wid & 1, warp_n = wid >> 1;

    const __half* tp[4] = {
        Ah + (size_t)b * 2048 * 1024 + (size_t)m0 * 1024,
        Al + (size_t)b * 2048 * 1024 + (size_t)m0 * 1024,
        Bh + (size_t)b * sBb + (size_t)n0 * 1024,
        Bl + (size_t)b * sBb + (size_t)n0 * 1024
    };

    float acc[2][4][4];
#pragma unroll
    for (int i = 0; i < 2; i++)
#pragma unroll
        for (int j = 0; j < 4; j++)
#pragma unroll
            for (int q = 0; q < 4; q++) acc[i][j][q] = 0.0f;

    const int x7 = lane & 7;
    const uint32_t aoff = (uint32_t)(warp_m * 32 + (lane & 15)) * 128;
    const int hlA = (lane >> 4) & 1;
    const uint32_t boff = (uint32_t)(warp_n * 32 + (lane & 7) + ((lane >> 4) & 1) * 8) * 128;
    const int hlB = (lane >> 3) & 1;
    uint32_t axo[4], bxo[4];
#pragma unroll
    for (int s = 0; s < 4; s++) {
        axo[s] = (uint32_t)(((s * 2 + hlA) ^ x7) * 16);
        bxo[s] = (uint32_t)(((s * 2 + hlB) ^ x7) * 16);
    }

    const int NC = 16;

    auto load_chunk = [&](int ch, int buf) {
#pragma unroll
        for (int i = 0; i < 12; i++) {
            const int o   = (i < 2) ? 0 : (i < 4) ? 1 : (i < 8) ? 2 : 3;
            const int sub = (i < 4) ? (i & 1) : (i & 3);
            const int idx = sub * 256 + tid;
            const int row = idx >> 3, gr = tid & 7;
            const __half* src = tp[o] + (size_t)row * 1024 + ch * 64 + gr * 8;
            const uint32_t tof = (o == 0) ? 0u : (o == 1) ? 8192u : (o == 2) ? 16384u : 32768u;
            const uint32_t dst = sb + (uint32_t)buf * 49152 + tof
                               + (uint32_t)row * 128 + (uint32_t)((gr ^ (row & 7)) * 16);
            asm volatile("cp.async.cg.shared.global [%0], [%1], 16;" :: "r"(dst), "l"(src));
        }
        asm volatile("cp.async.commit_group;");
    };

    load_chunk(0, 0);
    for (int ch = 0; ch < NC; ch++) {
        __syncthreads();
        if (ch + 1 < NC) {
            load_chunk(ch + 1, (ch + 1) & 1);
            asm volatile("cp.async.wait_group 1;" ::: "memory");
        } else {
            asm volatile("cp.async.wait_group 0;" ::: "memory");
        }
        __syncthreads();
        const uint32_t base = sb + (uint32_t)(ch & 1) * 49152;
        const uint32_t aB0 = base + aoff;
        const uint32_t aB1 = base + 8192 + aoff;
        const uint32_t bBh = base + 16384 + boff;
        const uint32_t bBl = base + 32768 + boff;
#pragma unroll
        for (int s = 0; s < 4; s++) {
            uint32_t a[2][2][4];
#pragma unroll
            for (int mf = 0; mf < 2; mf++) {
                LDSM4(a[mf][0], aB0 + mf * 2048 + axo[s]);
                LDSM4(a[mf][1], aB1 + mf * 2048 + axo[s]);
            }
            uint32_t bh[2][4], bl[2][4];
            LDSM4(bh[0], bBh + bxo[s]);
            LDSM4(bl[0], bBl + bxo[s]);
#pragma unroll
            for (int np = 0; np < 2; np++) {
                const int cur = np & 1;
                if (np < 1) {
                    LDSM4(bh[cur ^ 1], bBh + 2048 + bxo[s]);
                    LDSM4(bl[cur ^ 1], bBl + 2048 + bxo[s]);
                }
#pragma unroll
                for (int mf = 0; mf < 2; mf++) {
#pragma unroll
                    for (int h = 0; h < 2; h++) {
                        const int nf = np * 2 + h;
                        MMA_F16(acc[mf][nf], a[mf][0], bh[cur][2 * h], bh[cur][2 * h + 1]);
                        MMA_F16(acc[mf][nf], a[mf][0], bl[cur][2 * h], bl[cur][2 * h + 1]);
                        MMA_F16(acc[mf][nf], a[mf][1], bh[cur][2 * h], bh[cur][2 * h + 1]);
                    }
                }
            }
        }
    }
    asm volatile("cp.async.wait_group 0;" ::: "memory");

    const int rg = m0 + warp_m * 32 + (lane >> 2);
    const int cg = n0 + warp_n * 32 + (lane & 3) * 2;

    if (mode == 0) {
        __half* CH = Chi + cOff;
        __half* CL = Clo + cOff;
#pragma unroll
        for (int mf = 0; mf < 2; mf++) {
#pragma unroll
            for (int nf = 0; nf < 4; nf++) {
                const int R = rg + mf * 16;
                const int C0 = cg + nf * 8;
                float r0 = fmaxf(acc[mf][nf][0], 0.f), r1 = fmaxf(acc[mf][nf][1], 0.f);
                float r2 = fmaxf(acc[mf][nf][2], 0.f), r3 = fmaxf(acc[mf][nf][3], 0.f);
                __half h0, l0, h1, l1, h2, l2, h3, l3;
                split2h(r0, h0, l0); split2h(r1, h1, l1);
                split2h(r2, h2, l2); split2h(r3, h3, l3);
                uint32_t hp0 = (uint32_t)__half_as_ushort(h0) | ((uint32_t)__half_as_ushort(h1) << 16);
                uint32_t lp0 = (uint32_t)__half_as_ushort(l0) | ((uint32_t)__half_as_ushort(l1) << 16);
                uint32_t hp1 = (uint32_t)__half_as_ushort(h2) | ((uint32_t)__half_as_ushort(h3) << 16);
                uint32_t lp1 = (uint32_t)__half_as_ushort(l2) | ((uint32_t)__half_as_ushort(l3) << 16);
                *reinterpret_cast<uint32_t*>(CH + (size_t)R * ldc + C0) = hp0;
                *reinterpret_cast<uint32_t*>(CL + (size_t)R * ldc + C0) = lp0;
                *reinterpret_cast<uint32_t*>(CH + (size_t)(R + 8) * ldc + C0) = hp1;
                *reinterpret_cast<uint32_t*>(CL + (size_t)(R + 8) * ldc + C0) = lp1;
            }
        }
    } else {
        float* Co = C + cOff;
#pragma unroll
        for (int mf = 0; mf < 2; mf++) {
#pragma unroll
            for (int nf = 0; nf < 4; nf++) {
                const int R0 = rg + mf * 16, R1 = R0 + 8;
                const int C0 = cg + nf * 8;
                const bool c0v = C0 < cCol, c1v = (C0 + 1) < cCol;
                const bool r0v = R0 < cRow, r1v = R1 < cRow;
                float2 w0 = { (r0v && c0v) ? acc[mf][nf][0] : NEGV,
                              (r0v && c1v) ? acc[mf][nf][1] : NEGV };
                float2 w1 = { (r1v && c0v) ? acc[mf][nf][2] : NEGV,
                              (r1v && c1v) ? acc[mf][nf][3] : NEGV };
                *reinterpret_cast<float2*>(Co + (size_t)R0 * ldc + C0) = w0;
                *reinterpret_cast<float2*>(Co + (size_t)R1 * ldc + C0) = w1;
            }
        }
    }
}

// ====== attn GEMM (2-term): M64 N128 K-chunk 64, 3-stage (32KB/stage), occ 2 ======
__global__ __launch_bounds__(256, 2)
void attn_hmma_kernel(float* __restrict__ Cout)
{
    const int zz = blockIdx.z;
    const int sel = zz >> 4;
    const int b = zz & 15;
    const int m0 = blockIdx.y * 64, n0 = blockIdx.x * 128;

    const __half *Ah, *Al, *Bh;
    int Mlim, K, cRow;
    const int* scat;
    size_t cOff;
    if (sel == 0) {
        Ah = g_Phi; Al = g_Plo; Bh = g_yThi;
        Mlim = c_pad(g_cntXp[b]); K = c_pad(g_cntYp[b]);
        cRow = c_cnt(g_cntX[b]); scat = g_idxX + b * 2048;
        cOff = (size_t)b * 2048 * 1024;
    } else {
        Ah = g_Pchi; Al = g_Pclo; Bh = g_xThi;
        Mlim = c_pad(g_cntYp[b]); K = c_pad(g_cntXp[b]);
        cRow = c_cnt(g_cntY[b]); scat = g_idxY + b * 2048;
        cOff = (size_t)33554432 + (size_t)b * 2048 * 1024;
    }
    if (m0 >= Mlim) return;

    extern __shared__ __align__(16) char smem_raw[];
    const uint32_t sb = smem_u32(smem_raw);
    const int tid = threadIdx.x, wid = tid >> 5, lane = tid & 31;
    const int warp_m = wid & 1, warp_n = wid >> 1;

    const __half* tp[3] = {
        Ah + (size_t)b * 2048 * 2048 + (size_t)m0 * 2048,
        Al + (size_t)b * 2048 * 2048 + (size_t)m0 * 2048,
        Bh + (size_t)b * 1024 * 2048 + (size_t)n0 * 2048
    };

    float acc[2][4][4];
#pragma unroll
    for (int i = 0; i < 2; i++)
#pragma unroll
        for (int j = 0; j < 4; j++)
#pragma unroll
            for (int q = 0; q < 4; q++) acc[i][j][q] = 0.0f;

    const int x7 = lane & 7;
    const uint32_t aoff = (uint32_t)(warp_m * 32 + (lane & 15)) * 128;
    const int hlA = (lane >> 4) & 1;
    const uint32_t boff = (uint32_t)(warp_n * 32 + (lane & 7) + ((lane >> 4) & 1) * 8) * 128;
    const int hlB = (lane >> 3) & 1;
    uint32_t axo[4], bxo[4];
#pragma unroll
    for (int s = 0; s < 4; s++) {
        axo[s] = (uint32_t)(((s * 2 + hlA) ^ x7) * 16);
        bxo[s] = (uint32_t)(((s * 2 + hlB) ^ x7) * 16);
    }

    const int NC = K >> 6;     // K multiple of 128 -> NC >= 2

    auto load_chunk = [&](int ch, int buf) {
#pragma unroll
        for (int i = 0; i < 8; i++) {
            // i 0-1: Ahi(64r), 2-3: Alo(64r), 4-7: Bh(128r)
            const int o   = (i < 2) ? 0 : (i < 4) ? 1 : 2;
            const int sub = (i < 4) ? (i & 1) : (i & 3);
            const int idx = sub * 256 + tid;
            const int row = idx >> 3, gr = tid & 7;
            const __half* src = tp[o] + (size_t)row * 2048 + ch * 64 + gr * 8;
            const uint32_t tof = (o == 0) ? 0u : (o == 1) ? 8192u : 16384u;
            const uint32_t dst = sb + (uint32_t)buf * 32768 + tof
                               + (uint32_t)row * 128 + (uint32_t)((gr ^ (row & 7)) * 16);
            asm volatile("cp.async.cg.shared.global [%0], [%1], 16;" :: "r"(dst), "l"(src));
        }
        asm volatile("cp.async.commit_group;");
    };

    load_chunk(0, 0);
    load_chunk(1, 1);
    int cbuf = 0, pbuf = 2;
    for (int ch = 0; ch < NC; ch++) {
        __syncthreads();                              // pbuf free (consumed at ch-1)
        if (ch + 2 < NC) {
            load_chunk(ch + 2, pbuf);
            asm volatile("cp.async.wait_group 2;" ::: "memory");
        } else if (ch + 1 < NC) {
            asm volatile("cp.async.wait_group 1;" ::: "memory");
        } else {
            asm volatile("cp.async.wait_group 0;" ::: "memory");
        }
        __syncthreads();                              // ch's data visible
        const uint32_t base = sb + (uint32_t)cbuf * 32768;
        if (++cbuf == 3) cbuf = 0;
        if (++pbuf == 3) pbuf = 0;
        const uint32_t aB0 = base + aoff;
        const uint32_t aB1 = base + 8192 + aoff;
        const uint32_t bB  = base + 16384 + boff;
#pragma unroll
        for (int s = 0; s < 4; s++) {
            uint32_t a[2][2][4];
#pragma unroll
            for (int mf = 0; mf < 2; mf++) {
                LDSM4(a[mf][0], aB0 + mf * 2048 + axo[s]);
                LDSM4(a[mf][1], aB1 + mf * 2048 + axo[s]);
            }
            uint32_t bh[2][4];
            LDSM4(bh[0], bB + bxo[s]);
#pragma unroll
            for (int np = 0; np < 2; np++) {
                const int cur = np & 1;
                if (np < 1) LDSM4(bh[cur ^ 1], bB + 2048 + bxo[s]);
#pragma unroll
                for (int mf = 0; mf < 2; mf++) {
#pragma unroll
                    for (int h = 0; h < 2; h++) {
                        const int nf = np * 2 + h;
                        MMA_F16(acc[mf][nf], a[mf][0], bh[cur][2 * h], bh[cur][2 * h + 1]);
                        MMA_F16(acc[mf][nf], a[mf][1], bh[cur][2 * h], bh[cur][2 * h + 1]);
                    }
                }
            }
        }
    }
    asm volatile("cp.async.wait_group 0;" ::: "memory");

    // scatter epilogue
    const int rg = m0 + warp_m * 32 + (lane >> 2);
    const int cg = n0 + warp_n * 32 + (lane & 3) * 2;
    float* Co = Cout + cOff;
    int gr2[2][2];
#pragma unroll
    for (int mf = 0; mf < 2; mf++)
#pragma unroll
        for (int h = 0; h < 2; h++) {
            const int R = rg + mf * 16 + h * 8;
            gr2[mf][h] = (R < cRow) ? c_idx(scat[R]) : -1;
        }
#pragma unroll
    for (int mf = 0; mf < 2; mf++) {
#pragma unroll
        for (int nf = 0; nf < 4; nf++) {
            const int C0 = cg + nf * 8;
            if (gr2[mf][0] >= 0) {
                float2 w = { acc[mf][nf][0], acc[mf][nf][1] };
                *reinterpret_cast<float2*>(Co + (size_t)gr2[mf][0] * 1024 + C0) = w;
            }
            if (gr2[mf][1] >= 0) {
                float2 w = { acc[mf][nf][2], acc[mf][nf][3] };
                *reinterpret_cast<float2*>(Co + (size_t)gr2[mf][1] * 1024 + C0) = w;
            }
        }
    }
}

// =================================================================================
extern "C" void kernel_launch(void* const* d_in, const int* in_sizes, int n_in,
                              void* d_out, int out_size)
{
    (void)in_sizes; (void)n_in; (void)out_size;
    const float* x  = (const float*)d_in[0];
    const float* y  = (const float*)d_in[1];
    const void*  xm = d_in[2];
    const void*  ym = d_in[3];
    const float* Wx = (const float*)d_in[4];
    const float* Wy = (const float*)d_in[5];
    float* out = (float*)d_out;

    static const int SMEM_GEMM = 98304;   // gemm64: 2x49152 ; attn: 3x32768
    cudaFuncSetAttribute(gemm64_hmma_kernel, cudaFuncAttributeMaxDynamicSharedMemorySize, SMEM_GEMM);
    cudaFuncSetAttribute(attn_hmma_kernel, cudaFuncAttributeMaxDynamicSharedMemorySize, SMEM_GEMM);

    // 0-2
    build_idx_kernel<<<32, 256>>>(xm, ym);
    gather_split_both_kernel<<<dim3(16, 32, 32), 256>>>(x, y);
    split_plain_kernel<<<2048, 256>>>(Wx, Wy);
    // 3: merged projection GEMM (M64 K64) — ncu capture target
    gemm64_hmma_kernel<<<dim3(8, 32, 32), 256, SMEM_GEMM>>>(0, nullptr);
    // score (M64 K64, 3-term)
    gemm64_hmma_kernel<<<dim3(16, 32, 16), 256, SMEM_GEMM>>>(2, nullptr);
    // softmax passes
    row_softmax_kernel<<<dim3(2048, 16), 256>>>();
    colsoft_kernel<<<dim3(64, 16), dim3(32, 8)>>>();
    // merged attention GEMMs: M64 K64 3-stage kernel
    attn_hmma_kernel<<<dim3(8, 32, 32), 256, SMEM_GEMM>>>(out);
    // masked rows: exact means
    mean_kernel<<<dim3(4, 32), 256>>>(x, y);
    mean_fill_kernel<<<dim3(2048, 32), 256>>>(xm, ym, out);
}